// round 13
// baseline (speedup 1.0000x reference)
#include <cuda_runtime.h>
#include <cuda_bf16.h>
#include <math.h>

#define E_EDGES 200000
#define N_N     20000
#define KSLOT   20
#define HID     100
#define TDIM    100
#define EFD     128
#define FIN     228          // EFD + TDIM
#define RH      400
#define MROWS   (N_N*KSLOT)  // 400000
#define LN_EPS  1e-5f

// scratch (device globals; no allocation allowed)
__device__ float g_split[(size_t)MROWS * HID];  // x: scatter target, colmix in-place, residual
__device__ float g_y[(size_t)MROWS * HID];      // mixer output X2
__device__ float g_w1p[448 * 112];              // tf32+perm16 W1 [448][112]
__device__ float g_w2p[7 * 104 * 64];           // tf32+perm16 W2 chunks [7][104][64]
__device__ float g_wep[112 * 240];              // tf32+perm16 edge W [112][240]
__device__ float g_tw[128];                     // time-encode freqs (padded)

__device__ __forceinline__ float gelu_f(float x) {
    return 0.5f * x * (1.0f + erff(x * 0.70710678118654752f));
}

__device__ __forceinline__ unsigned f2tf(float v) {
    unsigned r;
    asm("cvt.rna.tf32.f32 %0, %1;" : "=r"(r) : "f"(v));
    return r;
}
__device__ __forceinline__ float f2tf_f(float v) { return __uint_as_float(f2tf(v)); }

// permute k within each 16-block: thread p's 4 frag elems (k = p, p+4, p+8, p+12) contiguous
__device__ __forceinline__ int kperm16(int k) {
    return (k & ~15) | (((k & 3) << 2) | ((k >> 2) & 3));
}

__device__ __forceinline__ void barpair(int id) {
    asm volatile("bar.sync %0, 64;" :: "r"(id) : "memory");
}

#define MMA_TF32(c,a0,a1,a2,a3,b0,b1) \
    asm volatile("mma.sync.aligned.m16n8k8.row.col.f32.tf32.tf32.f32 " \
        "{%0,%1,%2,%3}, {%4,%5,%6,%7}, {%8,%9}, {%0,%1,%2,%3};" \
        : "+f"(c[0]),"+f"(c[1]),"+f"(c[2]),"+f"(c[3]) \
        : "r"(a0),"r"(a1),"r"(a2),"r"(a3),"r"(b0),"r"(b1))

// ---------------------------------------------------------------- K0: init (zero split + all weight prep)
__global__ void k_init(const float* __restrict__ w1, const float* __restrict__ w2,
                       const float* __restrict__ lw) {
    int i = blockIdx.x * 256 + threadIdx.x;
    const int n4 = MROWS * HID / 4;            // 10,000,000
    if (i < n4) ((float4*)g_split)[i] = make_float4(0.f, 0.f, 0.f, 0.f);
    if (i < 448 * 112) {
        int ng = i / 112, k = i - ng * 112;
        g_w1p[ng * 112 + kperm16(k)] =
            f2tf_f((ng < RH && k < HID) ? w1[ng * HID + k] : 0.f);
    }
    if (i < 7 * 104 * 64) {
        int ch = i / (104 * 64);
        int r  = i - ch * 104 * 64;
        int n  = r >> 6, k = r & 63;
        g_w2p[(ch * 104 + n) * 64 + kperm16(k)] =
            f2tf_f((n < HID) ? w2[n * RH + ch * 64 + k] : 0.f);
    }
    if (i < 112 * 240) {
        int n = i / 240, k = i - n * 240;
        g_wep[n * 240 + kperm16(k)] =
            f2tf_f((n < HID && k < FIN) ? lw[n * FIN + k] : 0.f);
    }
    if (i < 128) g_tw[i] = (i < TDIM) ? exp10f(-(9.0f / 99.0f) * (float)i) : 0.f;
}

// ---------------------------------------------------------------- K1: edge MLP (tf32 mma) + scatter
// 64 edges/block, 256 threads = 8 warps = 4 m-groups (16 edges) x 2 n-halves.
#define ESA 240          // fs stride (240 mod 32 = 16 -> LDS.128 conflict-free)
#define EDGE_SMEM (64 * ESA * 4)   // 61440 B -> 2 blocks/SM

__global__ __launch_bounds__(256, 2) void k_edge(
    const float* __restrict__ ef, const float* __restrict__ et,
    const int* __restrict__ nid, const int* __restrict__ idxp,
    const float* __restrict__ lb)
{
    extern __shared__ float fs[];    // [64][240] tf32, perm16
    int tid = threadIdx.x;
    int e0 = blockIdx.x * 64;

    for (int o = tid; o < 64 * 32; o += 256) {
        int e = o >> 5, j4 = o & 31;
        float4 v = ((const float4*)ef)[(size_t)(e0 + e) * 32 + j4];
        float* dst = fs + e * ESA;
        int k0 = j4 * 4;
        dst[kperm16(k0)]     = f2tf_f(v.x);
        dst[kperm16(k0 + 1)] = f2tf_f(v.y);
        dst[kperm16(k0 + 2)] = f2tf_f(v.z);
        dst[kperm16(k0 + 3)] = f2tf_f(v.w);
    }
    for (int o = tid; o < 64 * 112; o += 256) {
        int e = o / 112, tt = o - e * 112;
        float val = 0.f;
        if (tt < TDIM) val = __cosf(et[e0 + e] * __ldg(g_tw + tt));
        fs[e * ESA + kperm16(128 + tt)] = f2tf_f(val);
    }
    __syncthreads();

    int warp = tid >> 5, lane = tid & 31;
    int q = lane >> 2, p = lane & 3;
    int mgrp = warp & 3, h = warp >> 2;
    int m0 = mgrp * 16;

    float acc[7][4];
#pragma unroll
    for (int i = 0; i < 7; i++)
#pragma unroll
        for (int j = 0; j < 4; j++) acc[i][j] = 0.f;

#pragma unroll
    for (int ks = 0; ks < 15; ks++) {          // 15 x k16 over K=240
        float4 a0 = *(const float4*)(fs + (m0 + q) * ESA + ks * 16 + 4 * p);
        float4 a1 = *(const float4*)(fs + (m0 + q + 8) * ESA + ks * 16 + 4 * p);
#pragma unroll
        for (int nt = 0; nt < 7; nt++) {
            float4 bv = *(const float4*)(g_wep + ((h * 7 + nt) * 8 + q) * ESA + ks * 16 + 4 * p);
            MMA_TF32(acc[nt],
                     __float_as_uint(a0.x), __float_as_uint(a1.x),
                     __float_as_uint(a0.y), __float_as_uint(a1.y),
                     __float_as_uint(bv.x), __float_as_uint(bv.y));
            MMA_TF32(acc[nt],
                     __float_as_uint(a0.z), __float_as_uint(a1.z),
                     __float_as_uint(a0.w), __float_as_uint(a1.w),
                     __float_as_uint(bv.z), __float_as_uint(bv.w));
        }
    }

    int e1 = e0 + m0 + q, e2 = e1 + 8;
    int pos1 = nid[e1] * KSLOT + idxp[e1];
    int pos2 = nid[e2] * KSLOT + idxp[e2];
#pragma unroll
    for (int nt = 0; nt < 7; nt++) {
        int col = (h * 7 + nt) * 8 + 2 * p;
        if (col < HID) {
            float b0 = __ldg(lb + col), b1 = __ldg(lb + col + 1);
            *(float2*)(g_split + (size_t)pos1 * HID + col) =
                make_float2(acc[nt][0] + b0, acc[nt][1] + b1);
            *(float2*)(g_split + (size_t)pos2 * HID + col) =
                make_float2(acc[nt][2] + b0, acc[nt][3] + b1);
        }
    }
}

// ---------------------------------------------------------------- K2: column mixer v3 (8 nodes/block)
#define CMX_SMEM ((8 * 2080 + 512) * 4)

__global__ __launch_bounds__(256) void k_colmix(
    const float* __restrict__ cg, const float* __restrict__ cb,
    const float* __restrict__ cw1, const float* __restrict__ cb1,
    const float* __restrict__ cw2, const float* __restrict__ cb2)
{
    extern __shared__ float sm2[];
    float* t   = sm2;                  // 8 nodes x [20][104]
    float* w1s = sm2 + 8 * 2080;       // [200]
    float* w2s = w1s + 200;            // [200]
    float* gs  = w2s + 200;            // [20]
    float* bs  = gs + 20;              // [20]
    float* b1s = bs + 20;              // [10]
    float* b2s = b1s + 10;             // [20]
    int tid = threadIdx.x;
    float* base = g_split + (size_t)blockIdx.x * 8 * KSLOT * HID;

    for (int o = tid; o < 200; o += 256) { w1s[o] = cw1[o]; w2s[o] = cw2[o]; }
    if (tid < 20) { gs[tid] = cg[tid]; bs[tid] = cb[tid]; b2s[tid] = cb2[tid]; }
    if (tid >= 32 && tid < 42) b1s[tid - 32] = cb1[tid - 32];

    for (int o = tid; o < 4000; o += 256) {
        int node = o / 500, r = o % 500;
        int k = r / 25, c4 = r - k * 25;
        *(float4*)(t + node * 2080 + k * 104 + c4 * 4) =
            *(const float4*)(base + (node * KSLOT + k) * HID + c4 * 4);
    }
    __syncthreads();

    int node = tid >> 5, lane = tid & 31;
    float* tb = t + node * 2080;
#pragma unroll
    for (int i = 0; i < 4; i++) {
        int c = lane + 32 * i;
        if (c < HID) {
            float v[KSLOT]; float s = 0.f;
#pragma unroll
            for (int k = 0; k < KSLOT; k++) { v[k] = tb[k * 104 + c]; s += v[k]; }
            float mu = s * (1.0f / KSLOT);
            float s2 = 0.f;
#pragma unroll
            for (int k = 0; k < KSLOT; k++) { float d = v[k] - mu; s2 += d * d; }
            float rs = rsqrtf(s2 * (1.0f / KSLOT) + LN_EPS);

            float vn[KSLOT];
#pragma unroll
            for (int k = 0; k < KSLOT; k++) vn[k] = (v[k] - mu) * rs * gs[k] + bs[k];

            float h1[10];
#pragma unroll
            for (int m = 0; m < 10; m++) {
                float a = b1s[m];
#pragma unroll
                for (int k = 0; k < KSLOT; k++) a += w1s[m * KSLOT + k] * vn[k];
                h1[m] = gelu_f(a);
            }
#pragma unroll
            for (int k = 0; k < KSLOT; k++) {
                float d = b2s[k];
#pragma unroll
                for (int m = 0; m < 10; m++) d += w2s[k * 10 + m] * h1[m];
                tb[k * 104 + c] = v[k] + d;
            }
        }
    }
    __syncthreads();

    for (int o = tid; o < 4000; o += 256) {
        int node = o / 500, r = o % 500;
        int k = r / 25, c4 = r - k * 25;
        *(float4*)(base + (node * KSLOT + k) * HID + c4 * 4) =
            *(const float4*)(t + node * 2080 + k * 104 + c4 * 4);
    }
}

// ---------------------------------------------------------------- K3: fused row mixer (tf32 mma, warp-pair cooperative)
// 128 rows/block, 256 threads = 4 pairs; pair owns 32 rows, warps split n-dim.
// Weights via LDG from pre-permuted g_w1p/g_w2p; pair syncs via named bar.sync(64).
#define SA 112    // Yn stride (112 mod 32 = 16 -> LDS.128 conflict-free)
#define SH 80     // Hs stride (64 + 16)
#define NCHUNK 7  // 448 = 7*64
#define MIX_SMEM (128 * (SA + SH) * 4)   // 98304 B -> 2 blocks/SM, 16 warps

__global__ __launch_bounds__(256, 2) void k_mixer(
    const float* __restrict__ lng, const float* __restrict__ lnb,
    const float* __restrict__ b1, const float* __restrict__ b2)
{
    extern __shared__ float smx[];
    float* Yn = smx;                  // [128][SA]  (per-pair 32-row regions)
    float* Hs = smx + 128 * SA;       // [128][SH]

    int tid  = threadIdx.x;
    int warp = tid >> 5, lane = tid & 31;
    int q = lane >> 2, p = lane & 3;
    int pair = warp >> 1;             // 0..3
    int h    = warp & 1;              // n-half within pair
    int m0   = pair * 32;
    int barid = pair + 1;
    size_t rowBase = (size_t)blockIdx.x * 128;

    // ---- rowLN -> Yn: each warp does 16 rows (warp*16 covers pair's 32 rows) ----
    for (int rr = 0; rr < 16; rr++) {
        int row = warp * 16 + rr;
        const float* x = g_split + (rowBase + row) * HID;
        float v[4]; float s = 0.f, s2 = 0.f;
#pragma unroll
        for (int i = 0; i < 4; i++) {
            int c = lane + 32 * i;
            v[i] = (c < HID) ? x[c] : 0.f;
            s += v[i]; s2 += v[i] * v[i];
        }
#pragma unroll
        for (int off = 16; off; off >>= 1) {
            s  += __shfl_xor_sync(0xffffffffu, s,  off);
            s2 += __shfl_xor_sync(0xffffffffu, s2, off);
        }
        float mu = s * 0.01f;
        float rs = rsqrtf(s2 * 0.01f - mu * mu + LN_EPS);
#pragma unroll
        for (int i = 0; i < 4; i++) {
            int c = lane + 32 * i;
            if (c < HID)
                Yn[row * SA + kperm16(c)] =
                    f2tf_f((v[i] - mu) * rs * __ldg(lng + c) + __ldg(lnb + c));
        }
        if (lane < SA - HID) Yn[row * SA + kperm16(HID + lane)] = 0.f;
    }
    barpair(barid);   // pair's Yn complete

    float acc2[2][7][4];
#pragma unroll
    for (int mt = 0; mt < 2; mt++)
#pragma unroll
        for (int i = 0; i < 7; i++)
#pragma unroll
            for (int j = 0; j < 4; j++) acc2[mt][i][j] = 0.f;

    const float* ya0 = Yn + (m0 + q) * SA + 4 * p;       // mt0 rows
    const float* ya1 = Yn + (m0 + 16 + q) * SA + 4 * p;  // mt1 rows
    const float* ha0 = Hs + (m0 + q) * SH + 4 * p;
    const float* ha1 = Hs + (m0 + 16 + q) * SH + 4 * p;

#pragma unroll 1
    for (int ch = 0; ch < NCHUNK; ch++) {
        // ---- GEMM1: this warp's 32-col half, all 32 rows ----
        float acc1[2][4][4];
#pragma unroll
        for (int mt = 0; mt < 2; mt++)
#pragma unroll
            for (int nt = 0; nt < 4; nt++)
#pragma unroll
                for (int j = 0; j < 4; j++) acc1[mt][nt][j] = 0.f;

        const float* w1c = g_w1p + (ch * 64 + h * 32 + q) * SA + 4 * p;
#pragma unroll
        for (int ks = 0; ks < 7; ks++) {
            float4 a00 = *(const float4*)(ya0 + ks * 16);
            float4 a01 = *(const float4*)(ya0 + 8 * SA + ks * 16);
            float4 a10 = *(const float4*)(ya1 + ks * 16);
            float4 a11 = *(const float4*)(ya1 + 8 * SA + ks * 16);
#pragma unroll
            for (int nt = 0; nt < 4; nt++) {
                float4 bv = *(const float4*)(w1c + nt * 8 * SA + ks * 16);
                MMA_TF32(acc1[0][nt],
                         __float_as_uint(a00.x), __float_as_uint(a01.x),
                         __float_as_uint(a00.y), __float_as_uint(a01.y),
                         __float_as_uint(bv.x), __float_as_uint(bv.y));
                MMA_TF32(acc1[0][nt],
                         __float_as_uint(a00.z), __float_as_uint(a01.z),
                         __float_as_uint(a00.w), __float_as_uint(a01.w),
                         __float_as_uint(bv.z), __float_as_uint(bv.w));
                MMA_TF32(acc1[1][nt],
                         __float_as_uint(a10.x), __float_as_uint(a11.x),
                         __float_as_uint(a10.y), __float_as_uint(a11.y),
                         __float_as_uint(bv.x), __float_as_uint(bv.y));
                MMA_TF32(acc1[1][nt],
                         __float_as_uint(a10.z), __float_as_uint(a11.z),
                         __float_as_uint(a10.w), __float_as_uint(a11.w),
                         __float_as_uint(bv.z), __float_as_uint(bv.w));
            }
        }

        barpair(barid);   // partner's GEMM2 reads of prev Hs complete

        // ---- bias + gelu -> Hs (this warp's cols, both m-tiles) ----
#pragma unroll
        for (int nt = 0; nt < 4; nt++) {
            int cl0 = h * 32 + nt * 8 + 2 * p;
            int cg0 = ch * 64 + cl0;
            float bb0 = (cg0     < RH) ? __ldg(b1 + cg0)     : 0.f;
            float bb1 = (cg0 + 1 < RH) ? __ldg(b1 + cg0 + 1) : 0.f;
            int ps0 = kperm16(cl0), ps1 = kperm16(cl0 + 1);
#pragma unroll
            for (int mt = 0; mt < 2; mt++) {
                float* h0 = Hs + (m0 + mt * 16 + q) * SH;
                float* h1 = Hs + (m0 + mt * 16 + q + 8) * SH;
                h0[ps0] = f2tf_f(gelu_f(acc1[mt][nt][0] + bb0));
                h0[ps1] = f2tf_f(gelu_f(acc1[mt][nt][1] + bb1));
                h1[ps0] = f2tf_f(gelu_f(acc1[mt][nt][2] + bb0));
                h1[ps1] = f2tf_f(gelu_f(acc1[mt][nt][3] + bb1));
            }
        }

        barpair(barid);   // pair's H complete

        // ---- GEMM2: this warp's output tiles (h=0: 0..6, h=1: 7..12), 32 rows ----
        const float* w2c = g_w2p + (ch * 104 + h * 56 + q) * 64 + 4 * p;
#pragma unroll
        for (int ks = 0; ks < 4; ks++) {
            float4 a00 = *(const float4*)(ha0 + ks * 16);
            float4 a01 = *(const float4*)(ha0 + 8 * SH + ks * 16);
            float4 a10 = *(const float4*)(ha1 + ks * 16);
            float4 a11 = *(const float4*)(ha1 + 8 * SH + ks * 16);
#pragma unroll
            for (int nt = 0; nt < 7; nt++) {
                if (nt < 7 - h) {
                    float4 bv = *(const float4*)(w2c + nt * 8 * 64 + ks * 16);
                    MMA_TF32(acc2[0][nt],
                             __float_as_uint(a00.x), __float_as_uint(a01.x),
                             __float_as_uint(a00.y), __float_as_uint(a01.y),
                             __float_as_uint(bv.x), __float_as_uint(bv.y));
                    MMA_TF32(acc2[0][nt],
                             __float_as_uint(a00.z), __float_as_uint(a01.z),
                             __float_as_uint(a00.w), __float_as_uint(a01.w),
                             __float_as_uint(bv.z), __float_as_uint(bv.w));
                    MMA_TF32(acc2[1][nt],
                             __float_as_uint(a10.x), __float_as_uint(a11.x),
                             __float_as_uint(a10.y), __float_as_uint(a11.y),
                             __float_as_uint(bv.x), __float_as_uint(bv.y));
                    MMA_TF32(acc2[1][nt],
                             __float_as_uint(a10.z), __float_as_uint(a11.z),
                             __float_as_uint(a10.w), __float_as_uint(a11.w),
                             __float_as_uint(bv.z), __float_as_uint(bv.w));
                }
            }
        }
    }

    // ---- epilogue: + b2 + residual -> g_y (fp32), 32 rows, this warp's cols ----
#pragma unroll
    for (int nt = 0; nt < 7; nt++) {
        if (nt < 7 - h) {
            int col = (h * 7 + nt) * 8 + 2 * p;
            if (col < HID) {
                float bb0 = __ldg(b2 + col), bb1 = __ldg(b2 + col + 1);
#pragma unroll
                for (int mt = 0; mt < 2; mt++) {
                    size_t r0 = rowBase + m0 + mt * 16 + q, r1 = r0 + 8;
                    float2 x0 = *(const float2*)(g_split + r0 * HID + col);
                    float2 x1 = *(const float2*)(g_split + r1 * HID + col);
                    *(float2*)(g_y + r0 * HID + col) =
                        make_float2(acc2[mt][nt][0] + bb0 + x0.x, acc2[mt][nt][1] + bb1 + x0.y);
                    *(float2*)(g_y + r1 * HID + col) =
                        make_float2(acc2[mt][nt][2] + bb0 + x1.x, acc2[mt][nt][3] + bb1 + x1.y);
                }
            }
        }
    }
}

// ---------------------------------------------------------------- K4: final LN + mean over K + out proj
__global__ __launch_bounds__(128) void k_final(
    const float* __restrict__ ng, const float* __restrict__ nb,
    const float* __restrict__ ow, const float* __restrict__ ob,
    float* __restrict__ out)
{
    __shared__ float Mp[4][HID];
    __shared__ float Ms[HID];
    int n = blockIdx.x;
    int tid = threadIdx.x, warp = tid >> 5, lane = tid & 31;

    float psum[4] = {0.f, 0.f, 0.f, 0.f};
    for (int rr = 0; rr < 5; rr++) {
        int k = warp * 5 + rr;
        const float* x = g_y + (size_t)(n * KSLOT + k) * HID;
        float v[4]; float s = 0.f, s2 = 0.f;
#pragma unroll
        for (int i = 0; i < 4; i++) {
            int c = lane + 32 * i;
            v[i] = (c < HID) ? x[c] : 0.f;
            s += v[i]; s2 += v[i] * v[i];
        }
#pragma unroll
        for (int off = 16; off; off >>= 1) {
            s  += __shfl_xor_sync(0xffffffffu, s,  off);
            s2 += __shfl_xor_sync(0xffffffffu, s2, off);
        }
        float mu = s * 0.01f;
        float rs = rsqrtf(s2 * 0.01f - mu * mu + LN_EPS);
#pragma unroll
        for (int i = 0; i < 4; i++) {
            int c = lane + 32 * i;
            if (c < HID) psum[i] += (v[i] - mu) * rs * ng[c] + nb[c];
        }
    }
#pragma unroll
    for (int i = 0; i < 4; i++) {
        int c = lane + 32 * i;
        if (c < HID) Mp[warp][c] = psum[i];
    }
    __syncthreads();
    if (tid < HID) Ms[tid] = (Mp[0][tid] + Mp[1][tid] + Mp[2][tid] + Mp[3][tid]) * (1.0f / KSLOT);
    __syncthreads();

    for (int o = warp; o < HID; o += 4) {
        float a = 0.f;
#pragma unroll
        for (int i = 0; i < 4; i++) {
            int c = lane + 32 * i;
            if (c < HID) a += Ms[c] * ow[o * HID + c];
        }
#pragma unroll
        for (int off = 16; off; off >>= 1) a += __shfl_xor_sync(0xffffffffu, a, off);
        if (lane == 0) out[(size_t)n * HID + o] = a + ob[o];
    }
}

// ---------------------------------------------------------------- launch
extern "C" void kernel_launch(void* const* d_in, const int* in_sizes, int n_in,
                              void* d_out, int out_size)
{
    const float* ef       = (const float*)d_in[0];
    const float* et       = (const float*)d_in[1];
    const int*   nid      = (const int*)  d_in[2];
    const int*   idx      = (const int*)  d_in[3];
    const float* lin_w    = (const float*)d_in[4];
    const float* lin_b    = (const float*)d_in[5];
    const float* col_ln_g = (const float*)d_in[6];
    const float* col_ln_b = (const float*)d_in[7];
    const float* col_w1   = (const float*)d_in[8];
    const float* col_b1   = (const float*)d_in[9];
    const float* col_w2   = (const float*)d_in[10];
    const float* col_b2   = (const float*)d_in[11];
    const float* row_ln_g = (const float*)d_in[12];
    const float* row_ln_b = (const float*)d_in[13];
    const float* row_w1   = (const float*)d_in[14];
    const float* row_b1   = (const float*)d_in[15];
    const float* row_w2   = (const float*)d_in[16];
    const float* row_b2   = (const float*)d_in[17];
    const float* norm_g   = (const float*)d_in[18];
    const float* norm_b   = (const float*)d_in[19];
    const float* out_w    = (const float*)d_in[20];
    const float* out_b    = (const float*)d_in[21];
    float* out = (float*)d_out;

    cudaFuncSetAttribute((const void*)k_edge,   cudaFuncAttributeMaxDynamicSharedMemorySize, EDGE_SMEM);
    cudaFuncSetAttribute((const void*)k_colmix, cudaFuncAttributeMaxDynamicSharedMemorySize, CMX_SMEM);
    cudaFuncSetAttribute((const void*)k_mixer,  cudaFuncAttributeMaxDynamicSharedMemorySize, MIX_SMEM);

    k_init<<<(MROWS * HID / 4 + 255) / 256, 256>>>(row_w1, row_w2, lin_w);
    k_edge<<<E_EDGES / 64, 256, EDGE_SMEM>>>(ef, et, nid, idx, lin_b);
    k_colmix<<<N_N / 8, 256, CMX_SMEM>>>(col_ln_g, col_ln_b, col_w1, col_b1, col_w2, col_b2);
    k_mixer<<<MROWS / 128, 256, MIX_SMEM>>>(row_ln_g, row_ln_b, row_b1, row_b2);
    k_final<<<N_N, 128>>>(norm_g, norm_b, out_w, out_b, out);
}

// round 14
// speedup vs baseline: 1.0621x; 1.0621x over previous
#include <cuda_runtime.h>
#include <cuda_bf16.h>
#include <math.h>

#define E_EDGES 200000
#define N_N     20000
#define KSLOT   20
#define HID     100
#define TDIM    100
#define EFD     128
#define FIN     228          // EFD + TDIM
#define RH      400
#define MROWS   (N_N*KSLOT)  // 400000
#define LN_EPS  1e-5f

// scratch (device globals; no allocation allowed)
__device__ float g_split[(size_t)MROWS * HID];  // x: scatter target, colmix in-place, residual
__device__ float g_y[(size_t)MROWS * HID];      // mixer output X2
// fragment-linear weights: [(ch,h)][nt][ks][lane][4] -> warp B-request = 512B contiguous
__device__ float g_w1p[7 * 2 * 4 * 7 * 128];    // 50176
__device__ float g_w2p[7 * 2 * 7 * 4 * 128];    // 50176
__device__ float g_wep[2 * 7 * 15 * 128];       // 26880
__device__ float g_tw[128];                     // time-encode freqs (padded)

__device__ __forceinline__ float gelu_f(float x) {
    return 0.5f * x * (1.0f + erff(x * 0.70710678118654752f));
}

__device__ __forceinline__ unsigned f2tf(float v) {
    unsigned r;
    asm("cvt.rna.tf32.f32 %0, %1;" : "=r"(r) : "f"(v));
    return r;
}
__device__ __forceinline__ float f2tf_f(float v) { return __uint_as_float(f2tf(v)); }

// permute k within each 16-block: thread p's 4 frag elems (k = p, p+4, p+8, p+12) contiguous
__device__ __forceinline__ int kperm16(int k) {
    return (k & ~15) | (((k & 3) << 2) | ((k >> 2) & 3));
}

__device__ __forceinline__ void barpair(int id) {
    asm volatile("bar.sync %0, 64;" :: "r"(id) : "memory");
}

#define MMA_TF32(c,a0,a1,a2,a3,b0,b1) \
    asm volatile("mma.sync.aligned.m16n8k8.row.col.f32.tf32.tf32.f32 " \
        "{%0,%1,%2,%3}, {%4,%5,%6,%7}, {%8,%9}, {%0,%1,%2,%3};" \
        : "+f"(c[0]),"+f"(c[1]),"+f"(c[2]),"+f"(c[3]) \
        : "r"(a0),"r"(a1),"r"(a2),"r"(a3),"r"(b0),"r"(b1))

// ---------------------------------------------------------------- K0: init (zero split + fragment-linear weight prep)
__global__ void k_init(const float* __restrict__ w1, const float* __restrict__ w2,
                       const float* __restrict__ lw) {
    int i = blockIdx.x * 256 + threadIdx.x;
    const int n4 = MROWS * HID / 4;            // 10,000,000
    if (i < n4) ((float4*)g_split)[i] = make_float4(0.f, 0.f, 0.f, 0.f);

    // W1: [(ch,h)][nt(4)][ks(7)][lane][e]; value W1[n][k], n=ch*64+h*32+nt*8+q, k=ks*16+p+4e
    if (i < 7 * 2 * 4 * 7 * 128) {
        int e = i & 3, lane = (i >> 2) & 31;
        int t = i >> 7;
        int ks = t % 7; t /= 7;
        int nt = t & 3; t >>= 2;
        int h = t & 1, ch = t >> 1;
        int q = lane >> 2, p = lane & 3;
        int n = ch * 64 + h * 32 + nt * 8 + q;
        int k = ks * 16 + p + 4 * e;
        g_w1p[i] = f2tf_f((n < RH && k < HID) ? w1[n * HID + k] : 0.f);
    }
    // W2: [(ch,h)][nt(7)][ks(4)][lane][e]; value W2[n][k], n=(h*7+nt)*8+q, k=ch*64+ks*16+p+4e
    if (i < 7 * 2 * 7 * 4 * 128) {
        int e = i & 3, lane = (i >> 2) & 31;
        int t = i >> 7;
        int ks = t & 3; t >>= 2;
        int nt = t % 7; t /= 7;
        int h = t & 1, ch = t >> 1;
        int q = lane >> 2, p = lane & 3;
        int n = (h * 7 + nt) * 8 + q;
        int k = ch * 64 + ks * 16 + p + 4 * e;
        g_w2p[i] = f2tf_f((n < HID && k < RH) ? w2[n * RH + k] : 0.f);
    }
    // edge W: [h(2)][nt(7)][ks(15)][lane][e]; value lw[n][k], n=(h*7+nt)*8+q, k=ks*16+p+4e
    if (i < 2 * 7 * 15 * 128) {
        int e = i & 3, lane = (i >> 2) & 31;
        int t = i >> 7;
        int ks = t % 15; t /= 15;
        int nt = t % 7;
        int h = t / 7;
        int q = lane >> 2, p = lane & 3;
        int n = (h * 7 + nt) * 8 + q;
        int k = ks * 16 + p + 4 * e;
        g_wep[i] = f2tf_f((n < HID && k < FIN) ? lw[n * FIN + k] : 0.f);
    }
    if (i < 128) g_tw[i] = (i < TDIM) ? exp10f(-(9.0f / 99.0f) * (float)i) : 0.f;
}

// ---------------------------------------------------------------- K1: edge MLP (tf32 mma) + scatter
// 64 edges/block, 256 threads = 8 warps = 4 m-groups (16 edges) x 2 n-halves.
#define ESA 240          // fs stride (240 mod 32 = 16 -> LDS.128 conflict-free)
#define EDGE_SMEM (64 * ESA * 4)   // 61440 B -> 2 blocks/SM

__global__ __launch_bounds__(256, 2) void k_edge(
    const float* __restrict__ ef, const float* __restrict__ et,
    const int* __restrict__ nid, const int* __restrict__ idxp,
    const float* __restrict__ lb)
{
    extern __shared__ float fs[];    // [64][240] tf32, perm16
    int tid = threadIdx.x;
    int e0 = blockIdx.x * 64;

    for (int o = tid; o < 64 * 32; o += 256) {
        int e = o >> 5, j4 = o & 31;
        float4 v = ((const float4*)ef)[(size_t)(e0 + e) * 32 + j4];
        float* dst = fs + e * ESA;
        int k0 = j4 * 4;
        dst[kperm16(k0)]     = f2tf_f(v.x);
        dst[kperm16(k0 + 1)] = f2tf_f(v.y);
        dst[kperm16(k0 + 2)] = f2tf_f(v.z);
        dst[kperm16(k0 + 3)] = f2tf_f(v.w);
    }
    for (int o = tid; o < 64 * 112; o += 256) {
        int e = o / 112, tt = o - e * 112;
        float val = 0.f;
        if (tt < TDIM) val = __cosf(et[e0 + e] * __ldg(g_tw + tt));
        fs[e * ESA + kperm16(128 + tt)] = f2tf_f(val);
    }
    __syncthreads();

    int warp = tid >> 5, lane = tid & 31;
    int q = lane >> 2, p = lane & 3;
    int mgrp = warp & 3, h = warp >> 2;
    int m0 = mgrp * 16;

    float acc[7][4];
#pragma unroll
    for (int i = 0; i < 7; i++)
#pragma unroll
        for (int j = 0; j < 4; j++) acc[i][j] = 0.f;

    const float* web = g_wep + (h * 7) * 15 * 128 + lane * 4;
#pragma unroll
    for (int ks = 0; ks < 15; ks++) {          // 15 x k16 over K=240
        float4 a0 = *(const float4*)(fs + (m0 + q) * ESA + ks * 16 + 4 * p);
        float4 a1 = *(const float4*)(fs + (m0 + q + 8) * ESA + ks * 16 + 4 * p);
#pragma unroll
        for (int nt = 0; nt < 7; nt++) {
            float4 bv = *(const float4*)(web + (nt * 15 + ks) * 128);
            MMA_TF32(acc[nt],
                     __float_as_uint(a0.x), __float_as_uint(a1.x),
                     __float_as_uint(a0.y), __float_as_uint(a1.y),
                     __float_as_uint(bv.x), __float_as_uint(bv.y));
            MMA_TF32(acc[nt],
                     __float_as_uint(a0.z), __float_as_uint(a1.z),
                     __float_as_uint(a0.w), __float_as_uint(a1.w),
                     __float_as_uint(bv.z), __float_as_uint(bv.w));
        }
    }

    int e1 = e0 + m0 + q, e2 = e1 + 8;
    int pos1 = nid[e1] * KSLOT + idxp[e1];
    int pos2 = nid[e2] * KSLOT + idxp[e2];
#pragma unroll
    for (int nt = 0; nt < 7; nt++) {
        int col = (h * 7 + nt) * 8 + 2 * p;
        if (col < HID) {
            float b0 = __ldg(lb + col), b1 = __ldg(lb + col + 1);
            *(float2*)(g_split + (size_t)pos1 * HID + col) =
                make_float2(acc[nt][0] + b0, acc[nt][1] + b1);
            *(float2*)(g_split + (size_t)pos2 * HID + col) =
                make_float2(acc[nt][2] + b0, acc[nt][3] + b1);
        }
    }
}

// ---------------------------------------------------------------- K2: column mixer v3 (8 nodes/block)
#define CMX_SMEM ((8 * 2080 + 512) * 4)

__global__ __launch_bounds__(256) void k_colmix(
    const float* __restrict__ cg, const float* __restrict__ cb,
    const float* __restrict__ cw1, const float* __restrict__ cb1,
    const float* __restrict__ cw2, const float* __restrict__ cb2)
{
    extern __shared__ float sm2[];
    float* t   = sm2;                  // 8 nodes x [20][104]
    float* w1s = sm2 + 8 * 2080;       // [200]
    float* w2s = w1s + 200;            // [200]
    float* gs  = w2s + 200;            // [20]
    float* bs  = gs + 20;              // [20]
    float* b1s = bs + 20;              // [10]
    float* b2s = b1s + 10;             // [20]
    int tid = threadIdx.x;
    float* base = g_split + (size_t)blockIdx.x * 8 * KSLOT * HID;

    for (int o = tid; o < 200; o += 256) { w1s[o] = cw1[o]; w2s[o] = cw2[o]; }
    if (tid < 20) { gs[tid] = cg[tid]; bs[tid] = cb[tid]; b2s[tid] = cb2[tid]; }
    if (tid >= 32 && tid < 42) b1s[tid - 32] = cb1[tid - 32];

    for (int o = tid; o < 4000; o += 256) {
        int node = o / 500, r = o % 500;
        int k = r / 25, c4 = r - k * 25;
        *(float4*)(t + node * 2080 + k * 104 + c4 * 4) =
            *(const float4*)(base + (node * KSLOT + k) * HID + c4 * 4);
    }
    __syncthreads();

    int node = tid >> 5, lane = tid & 31;
    float* tb = t + node * 2080;
#pragma unroll
    for (int i = 0; i < 4; i++) {
        int c = lane + 32 * i;
        if (c < HID) {
            float v[KSLOT]; float s = 0.f;
#pragma unroll
            for (int k = 0; k < KSLOT; k++) { v[k] = tb[k * 104 + c]; s += v[k]; }
            float mu = s * (1.0f / KSLOT);
            float s2 = 0.f;
#pragma unroll
            for (int k = 0; k < KSLOT; k++) { float d = v[k] - mu; s2 += d * d; }
            float rs = rsqrtf(s2 * (1.0f / KSLOT) + LN_EPS);

            float vn[KSLOT];
#pragma unroll
            for (int k = 0; k < KSLOT; k++) vn[k] = (v[k] - mu) * rs * gs[k] + bs[k];

            float h1[10];
#pragma unroll
            for (int m = 0; m < 10; m++) {
                float a = b1s[m];
#pragma unroll
                for (int k = 0; k < KSLOT; k++) a += w1s[m * KSLOT + k] * vn[k];
                h1[m] = gelu_f(a);
            }
#pragma unroll
            for (int k = 0; k < KSLOT; k++) {
                float d = b2s[k];
#pragma unroll
                for (int m = 0; m < 10; m++) d += w2s[k * 10 + m] * h1[m];
                tb[k * 104 + c] = v[k] + d;
            }
        }
    }
    __syncthreads();

    for (int o = tid; o < 4000; o += 256) {
        int node = o / 500, r = o % 500;
        int k = r / 25, c4 = r - k * 25;
        *(float4*)(base + (node * KSLOT + k) * HID + c4 * 4) =
            *(const float4*)(t + node * 2080 + k * 104 + c4 * 4);
    }
}

// ---------------------------------------------------------------- K3: fused row mixer (tf32 mma, warp-pair cooperative)
// 64 rows/block, 128 threads = 2 pairs; pair owns 32 rows, warps split n-dim.
// Weights: fragment-linear LDG (one 512B contiguous block per warp request).
#define SA 112    // Yn stride (112 mod 32 = 16 -> LDS.128 conflict-free)
#define SH 80     // Hs stride (64 + 16)
#define NCHUNK 7  // 448 = 7*64
#define MIX_SMEM ((64*SA + 64*SH) * 4)   // 49152 B -> 4 blocks/SM

__global__ __launch_bounds__(128, 4) void k_mixer(
    const float* __restrict__ lng, const float* __restrict__ lnb,
    const float* __restrict__ b1, const float* __restrict__ b2)
{
    extern __shared__ float smx[];
    float* Yn = smx;                  // [64][SA]  (per-pair 32-row regions)
    float* Hs = smx + 64 * SA;        // [64][SH]

    int tid  = threadIdx.x;
    int warp = tid >> 5, lane = tid & 31;
    int q = lane >> 2, p = lane & 3;
    int pair = warp >> 1;             // 0,1
    int h    = warp & 1;              // n-half within pair
    int m0   = pair * 32;
    int barid = pair + 1;
    size_t rowBase = (size_t)blockIdx.x * 64;

    // ---- rowLN -> Yn: each warp does 16 rows (warp*16 covers pair's 32 rows) ----
    for (int rr = 0; rr < 16; rr++) {
        int row = warp * 16 + rr;
        const float* x = g_split + (rowBase + row) * HID;
        float v[4]; float s = 0.f, s2 = 0.f;
#pragma unroll
        for (int i = 0; i < 4; i++) {
            int c = lane + 32 * i;
            v[i] = (c < HID) ? x[c] : 0.f;
            s += v[i]; s2 += v[i] * v[i];
        }
#pragma unroll
        for (int off = 16; off; off >>= 1) {
            s  += __shfl_xor_sync(0xffffffffu, s,  off);
            s2 += __shfl_xor_sync(0xffffffffu, s2, off);
        }
        float mu = s * 0.01f;
        float rs = rsqrtf(s2 * 0.01f - mu * mu + LN_EPS);
#pragma unroll
        for (int i = 0; i < 4; i++) {
            int c = lane + 32 * i;
            if (c < HID)
                Yn[row * SA + kperm16(c)] =
                    f2tf_f((v[i] - mu) * rs * __ldg(lng + c) + __ldg(lnb + c));
        }
        if (lane < SA - HID) Yn[row * SA + kperm16(HID + lane)] = 0.f;
    }
    barpair(barid);   // pair's Yn complete

    float acc2[2][7][4];
#pragma unroll
    for (int mt = 0; mt < 2; mt++)
#pragma unroll
        for (int i = 0; i < 7; i++)
#pragma unroll
            for (int j = 0; j < 4; j++) acc2[mt][i][j] = 0.f;

    const float* ya0 = Yn + (m0 + q) * SA + 4 * p;       // mt0 rows
    const float* ya1 = Yn + (m0 + 16 + q) * SA + 4 * p;  // mt1 rows
    const float* ha0 = Hs + (m0 + q) * SH + 4 * p;
    const float* ha1 = Hs + (m0 + 16 + q) * SH + 4 * p;

#pragma unroll 1
    for (int ch = 0; ch < NCHUNK; ch++) {
        // ---- GEMM1: this warp's 32-col half, all 32 rows ----
        float acc1[2][4][4];
#pragma unroll
        for (int mt = 0; mt < 2; mt++)
#pragma unroll
            for (int nt = 0; nt < 4; nt++)
#pragma unroll
                for (int j = 0; j < 4; j++) acc1[mt][nt][j] = 0.f;

        const float* w1c = g_w1p + (ch * 2 + h) * 28 * 128 + lane * 4;
#pragma unroll
        for (int ks = 0; ks < 7; ks++) {
            float4 a00 = *(const float4*)(ya0 + ks * 16);
            float4 a01 = *(const float4*)(ya0 + 8 * SA + ks * 16);
            float4 a10 = *(const float4*)(ya1 + ks * 16);
            float4 a11 = *(const float4*)(ya1 + 8 * SA + ks * 16);
#pragma unroll
            for (int nt = 0; nt < 4; nt++) {
                float4 bv = *(const float4*)(w1c + (nt * 7 + ks) * 128);
                MMA_TF32(acc1[0][nt],
                         __float_as_uint(a00.x), __float_as_uint(a01.x),
                         __float_as_uint(a00.y), __float_as_uint(a01.y),
                         __float_as_uint(bv.x), __float_as_uint(bv.y));
                MMA_TF32(acc1[0][nt],
                         __float_as_uint(a00.z), __float_as_uint(a01.z),
                         __float_as_uint(a00.w), __float_as_uint(a01.w),
                         __float_as_uint(bv.z), __float_as_uint(bv.w));
                MMA_TF32(acc1[1][nt],
                         __float_as_uint(a10.x), __float_as_uint(a11.x),
                         __float_as_uint(a10.y), __float_as_uint(a11.y),
                         __float_as_uint(bv.x), __float_as_uint(bv.y));
                MMA_TF32(acc1[1][nt],
                         __float_as_uint(a10.z), __float_as_uint(a11.z),
                         __float_as_uint(a10.w), __float_as_uint(a11.w),
                         __float_as_uint(bv.z), __float_as_uint(bv.w));
            }
        }

        barpair(barid);   // partner's GEMM2 reads of prev Hs complete

        // ---- bias + gelu -> Hs (this warp's cols, both m-tiles) ----
#pragma unroll
        for (int nt = 0; nt < 4; nt++) {
            int cl0 = h * 32 + nt * 8 + 2 * p;
            int cg0 = ch * 64 + cl0;
            float bb0 = (cg0     < RH) ? __ldg(b1 + cg0)     : 0.f;
            float bb1 = (cg0 + 1 < RH) ? __ldg(b1 + cg0 + 1) : 0.f;
            int ps0 = kperm16(cl0), ps1 = kperm16(cl0 + 1);
#pragma unroll
            for (int mt = 0; mt < 2; mt++) {
                float* h0 = Hs + (m0 + mt * 16 + q) * SH;
                float* h1 = Hs + (m0 + mt * 16 + q + 8) * SH;
                h0[ps0] = f2tf_f(gelu_f(acc1[mt][nt][0] + bb0));
                h0[ps1] = f2tf_f(gelu_f(acc1[mt][nt][1] + bb1));
                h1[ps0] = f2tf_f(gelu_f(acc1[mt][nt][2] + bb0));
                h1[ps1] = f2tf_f(gelu_f(acc1[mt][nt][3] + bb1));
            }
        }

        barpair(barid);   // pair's H complete

        // ---- GEMM2: this warp's output tiles (h=0: 0..6, h=1: 7..12), 32 rows ----
        const float* w2c = g_w2p + (ch * 2 + h) * 28 * 128 + lane * 4;
#pragma unroll
        for (int ks = 0; ks < 4; ks++) {
            float4 a00 = *(const float4*)(ha0 + ks * 16);
            float4 a01 = *(const float4*)(ha0 + 8 * SH + ks * 16);
            float4 a10 = *(const float4*)(ha1 + ks * 16);
            float4 a11 = *(const float4*)(ha1 + 8 * SH + ks * 16);
#pragma unroll
            for (int nt = 0; nt < 7; nt++) {
                if (nt < 7 - h) {
                    float4 bv = *(const float4*)(w2c + (nt * 4 + ks) * 128);
                    MMA_TF32(acc2[0][nt],
                             __float_as_uint(a00.x), __float_as_uint(a01.x),
                             __float_as_uint(a00.y), __float_as_uint(a01.y),
                             __float_as_uint(bv.x), __float_as_uint(bv.y));
                    MMA_TF32(acc2[0][nt],
                             __float_as_uint(a00.z), __float_as_uint(a01.z),
                             __float_as_uint(a00.w), __float_as_uint(a01.w),
                             __float_as_uint(bv.z), __float_as_uint(bv.w));
                    MMA_TF32(acc2[1][nt],
                             __float_as_uint(a10.x), __float_as_uint(a11.x),
                             __float_as_uint(a10.y), __float_as_uint(a11.y),
                             __float_as_uint(bv.x), __float_as_uint(bv.y));
                    MMA_TF32(acc2[1][nt],
                             __float_as_uint(a10.z), __float_as_uint(a11.z),
                             __float_as_uint(a10.w), __float_as_uint(a11.w),
                             __float_as_uint(bv.z), __float_as_uint(bv.w));
                }
            }
        }
    }

    // ---- epilogue: + b2 + residual -> g_y (fp32), 32 rows, this warp's cols ----
#pragma unroll
    for (int nt = 0; nt < 7; nt++) {
        if (nt < 7 - h) {
            int col = (h * 7 + nt) * 8 + 2 * p;
            if (col < HID) {
                float bb0 = __ldg(b2 + col), bb1 = __ldg(b2 + col + 1);
#pragma unroll
                for (int mt = 0; mt < 2; mt++) {
                    size_t r0 = rowBase + m0 + mt * 16 + q, r1 = r0 + 8;
                    float2 x0 = *(const float2*)(g_split + r0 * HID + col);
                    float2 x1 = *(const float2*)(g_split + r1 * HID + col);
                    *(float2*)(g_y + r0 * HID + col) =
                        make_float2(acc2[mt][nt][0] + bb0 + x0.x, acc2[mt][nt][1] + bb1 + x0.y);
                    *(float2*)(g_y + r1 * HID + col) =
                        make_float2(acc2[mt][nt][2] + bb0 + x1.x, acc2[mt][nt][3] + bb1 + x1.y);
                }
            }
        }
    }
}

// ---------------------------------------------------------------- K4: final LN + mean over K + out proj
__global__ __launch_bounds__(128) void k_final(
    const float* __restrict__ ng, const float* __restrict__ nb,
    const float* __restrict__ ow, const float* __restrict__ ob,
    float* __restrict__ out)
{
    __shared__ float Mp[4][HID];
    __shared__ float Ms[HID];
    int n = blockIdx.x;
    int tid = threadIdx.x, warp = tid >> 5, lane = tid & 31;

    float psum[4] = {0.f, 0.f, 0.f, 0.f};
    for (int rr = 0; rr < 5; rr++) {
        int k = warp * 5 + rr;
        const float* x = g_y + (size_t)(n * KSLOT + k) * HID;
        float v[4]; float s = 0.f, s2 = 0.f;
#pragma unroll
        for (int i = 0; i < 4; i++) {
            int c = lane + 32 * i;
            v[i] = (c < HID) ? x[c] : 0.f;
            s += v[i]; s2 += v[i] * v[i];
        }
#pragma unroll
        for (int off = 16; off; off >>= 1) {
            s  += __shfl_xor_sync(0xffffffffu, s,  off);
            s2 += __shfl_xor_sync(0xffffffffu, s2, off);
        }
        float mu = s * 0.01f;
        float rs = rsqrtf(s2 * 0.01f - mu * mu + LN_EPS);
#pragma unroll
        for (int i = 0; i < 4; i++) {
            int c = lane + 32 * i;
            if (c < HID) psum[i] += (v[i] - mu) * rs * ng[c] + nb[c];
        }
    }
#pragma unroll
    for (int i = 0; i < 4; i++) {
        int c = lane + 32 * i;
        if (c < HID) Mp[warp][c] = psum[i];
    }
    __syncthreads();
    if (tid < HID) Ms[tid] = (Mp[0][tid] + Mp[1][tid] + Mp[2][tid] + Mp[3][tid]) * (1.0f / KSLOT);
    __syncthreads();

    for (int o = warp; o < HID; o += 4) {
        float a = 0.f;
#pragma unroll
        for (int i = 0; i < 4; i++) {
            int c = lane + 32 * i;
            if (c < HID) a += Ms[c] * ow[o * HID + c];
        }
#pragma unroll
        for (int off = 16; off; off >>= 1) a += __shfl_xor_sync(0xffffffffu, a, off);
        if (lane == 0) out[(size_t)n * HID + o] = a + ob[o];
    }
}

// ---------------------------------------------------------------- launch
extern "C" void kernel_launch(void* const* d_in, const int* in_sizes, int n_in,
                              void* d_out, int out_size)
{
    const float* ef       = (const float*)d_in[0];
    const float* et       = (const float*)d_in[1];
    const int*   nid      = (const int*)  d_in[2];
    const int*   idx      = (const int*)  d_in[3];
    const float* lin_w    = (const float*)d_in[4];
    const float* lin_b    = (const float*)d_in[5];
    const float* col_ln_g = (const float*)d_in[6];
    const float* col_ln_b = (const float*)d_in[7];
    const float* col_w1   = (const float*)d_in[8];
    const float* col_b1   = (const float*)d_in[9];
    const float* col_w2   = (const float*)d_in[10];
    const float* col_b2   = (const float*)d_in[11];
    const float* row_ln_g = (const float*)d_in[12];
    const float* row_ln_b = (const float*)d_in[13];
    const float* row_w1   = (const float*)d_in[14];
    const float* row_b1   = (const float*)d_in[15];
    const float* row_w2   = (const float*)d_in[16];
    const float* row_b2   = (const float*)d_in[17];
    const float* norm_g   = (const float*)d_in[18];
    const float* norm_b   = (const float*)d_in[19];
    const float* out_w    = (const float*)d_in[20];
    const float* out_b    = (const float*)d_in[21];
    float* out = (float*)d_out;

    cudaFuncSetAttribute((const void*)k_edge,   cudaFuncAttributeMaxDynamicSharedMemorySize, EDGE_SMEM);
    cudaFuncSetAttribute((const void*)k_colmix, cudaFuncAttributeMaxDynamicSharedMemorySize, CMX_SMEM);
    cudaFuncSetAttribute((const void*)k_mixer,  cudaFuncAttributeMaxDynamicSharedMemorySize, MIX_SMEM);

    k_init<<<(MROWS * HID / 4 + 255) / 256, 256>>>(row_w1, row_w2, lin_w);
    k_edge<<<E_EDGES / 64, 256, EDGE_SMEM>>>(ef, et, nid, idx, lin_b);
    k_colmix<<<N_N / 8, 256, CMX_SMEM>>>(col_ln_g, col_ln_b, col_w1, col_b1, col_w2, col_b2);
    k_mixer<<<MROWS / 64, 128, MIX_SMEM>>>(row_ln_g, row_ln_b, row_b1, row_b2);
    k_final<<<N_N, 128>>>(norm_g, norm_b, out_w, out_b, out);
}

// round 15
// speedup vs baseline: 1.0977x; 1.0335x over previous
#include <cuda_runtime.h>
#include <cuda_bf16.h>
#include <math.h>

#define E_EDGES 200000
#define N_N     20000
#define KSLOT   20
#define HID     100
#define TDIM    100
#define EFD     128
#define FIN     228          // EFD + TDIM
#define RH      400
#define MROWS   (N_N*KSLOT)  // 400000
#define LN_EPS  1e-5f

// scratch (device globals; no allocation allowed)
__device__ float g_split[(size_t)MROWS * HID];  // x: scatter target, colmix in-place, residual
__device__ float g_y[(size_t)MROWS * HID];      // mixer output X2
// fragment-linear weights: [(ch,h)][nt][ks][lane][4] -> warp B-request = 512B contiguous
__device__ float g_w1p[7 * 2 * 4 * 7 * 128];    // 50176
__device__ float g_w2p[7 * 2 * 7 * 4 * 128];    // 50176
__device__ float g_wep[2 * 7 * 15 * 128];       // 26880
__device__ float g_tw[128];                     // time-encode freqs (padded)

// fast gelu: tanh-form with HW tanh.approx (sm_75+), ~6 instr vs ~20 for erff
__device__ __forceinline__ float gelu_fast(float x) {
    float u = x * (0.7978845608028654f + 0.035677408136300125f * x * x);
    float t;
    asm("tanh.approx.f32 %0, %1;" : "=f"(t) : "f"(u));
    return 0.5f * x * (1.0f + t);
}

__device__ __forceinline__ unsigned f2tf(float v) {
    unsigned r;
    asm("cvt.rna.tf32.f32 %0, %1;" : "=r"(r) : "f"(v));
    return r;
}
__device__ __forceinline__ float f2tf_f(float v) { return __uint_as_float(f2tf(v)); }

// permute k within each 16-block: thread p's 4 frag elems (k = p, p+4, p+8, p+12) contiguous
__device__ __forceinline__ int kperm16(int k) {
    return (k & ~15) | (((k & 3) << 2) | ((k >> 2) & 3));
}

__device__ __forceinline__ void barpair(int id) {
    asm volatile("bar.sync %0, 64;" :: "r"(id) : "memory");
}

#define MMA_TF32(c,a0,a1,a2,a3,b0,b1) \
    asm volatile("mma.sync.aligned.m16n8k8.row.col.f32.tf32.tf32.f32 " \
        "{%0,%1,%2,%3}, {%4,%5,%6,%7}, {%8,%9}, {%0,%1,%2,%3};" \
        : "+f"(c[0]),"+f"(c[1]),"+f"(c[2]),"+f"(c[3]) \
        : "r"(a0),"r"(a1),"r"(a2),"r"(a3),"r"(b0),"r"(b1))

// ---------------------------------------------------------------- K0: init (zero split + fragment-linear weight prep)
__global__ void k_init(const float* __restrict__ w1, const float* __restrict__ w2,
                       const float* __restrict__ lw) {
    int i = blockIdx.x * 256 + threadIdx.x;
    const int n4 = MROWS * HID / 4;            // 10,000,000
    if (i < n4) ((float4*)g_split)[i] = make_float4(0.f, 0.f, 0.f, 0.f);

    // W1: [(ch,h)][nt(4)][ks(7)][lane][e]; value W1[n][k], n=ch*64+h*32+nt*8+q, k=ks*16+p+4e
    if (i < 7 * 2 * 4 * 7 * 128) {
        int e = i & 3, lane = (i >> 2) & 31;
        int t = i >> 7;
        int ks = t % 7; t /= 7;
        int nt = t & 3; t >>= 2;
        int h = t & 1, ch = t >> 1;
        int q = lane >> 2, p = lane & 3;
        int n = ch * 64 + h * 32 + nt * 8 + q;
        int k = ks * 16 + p + 4 * e;
        g_w1p[i] = f2tf_f((n < RH && k < HID) ? w1[n * HID + k] : 0.f);
    }
    // W2: [(ch,h)][nt(7)][ks(4)][lane][e]; value W2[n][k], n=(h*7+nt)*8+q, k=ch*64+ks*16+p+4e
    if (i < 7 * 2 * 7 * 4 * 128) {
        int e = i & 3, lane = (i >> 2) & 31;
        int t = i >> 7;
        int ks = t & 3; t >>= 2;
        int nt = t % 7; t /= 7;
        int h = t & 1, ch = t >> 1;
        int q = lane >> 2, p = lane & 3;
        int n = (h * 7 + nt) * 8 + q;
        int k = ch * 64 + ks * 16 + p + 4 * e;
        g_w2p[i] = f2tf_f((n < HID && k < RH) ? w2[n * RH + k] : 0.f);
    }
    // edge W: [h(2)][nt(7)][ks(15)][lane][e]; value lw[n][k], n=(h*7+nt)*8+q, k=ks*16+p+4e
    if (i < 2 * 7 * 15 * 128) {
        int e = i & 3, lane = (i >> 2) & 31;
        int t = i >> 7;
        int ks = t % 15; t /= 15;
        int nt = t % 7;
        int h = t / 7;
        int q = lane >> 2, p = lane & 3;
        int n = (h * 7 + nt) * 8 + q;
        int k = ks * 16 + p + 4 * e;
        g_wep[i] = f2tf_f((n < HID && k < FIN) ? lw[n * FIN + k] : 0.f);
    }
    if (i < 128) g_tw[i] = (i < TDIM) ? exp10f(-(9.0f / 99.0f) * (float)i) : 0.f;
}

// ---------------------------------------------------------------- K1: edge MLP (tf32 mma) + scatter
// 64 edges/block, 256 threads = 8 warps = 4 m-groups (16 edges) x 2 n-halves.
#define ESA 240          // fs stride (240 mod 32 = 16 -> LDS.128 conflict-free)
#define EDGE_SMEM (64 * ESA * 4)   // 61440 B -> 2 blocks/SM

__global__ __launch_bounds__(256, 2) void k_edge(
    const float* __restrict__ ef, const float* __restrict__ et,
    const int* __restrict__ nid, const int* __restrict__ idxp,
    const float* __restrict__ lb)
{
    extern __shared__ float fs[];    // [64][240] tf32, perm16
    int tid = threadIdx.x;
    int e0 = blockIdx.x * 64;

    for (int o = tid; o < 64 * 32; o += 256) {
        int e = o >> 5, j4 = o & 31;
        float4 v = ((const float4*)ef)[(size_t)(e0 + e) * 32 + j4];
        float* dst = fs + e * ESA;
        int k0 = j4 * 4;
        dst[kperm16(k0)]     = f2tf_f(v.x);
        dst[kperm16(k0 + 1)] = f2tf_f(v.y);
        dst[kperm16(k0 + 2)] = f2tf_f(v.z);
        dst[kperm16(k0 + 3)] = f2tf_f(v.w);
    }
    for (int o = tid; o < 64 * 112; o += 256) {
        int e = o / 112, tt = o - e * 112;
        float val = 0.f;
        if (tt < TDIM) val = __cosf(et[e0 + e] * __ldg(g_tw + tt));
        fs[e * ESA + kperm16(128 + tt)] = f2tf_f(val);
    }
    __syncthreads();

    int warp = tid >> 5, lane = tid & 31;
    int q = lane >> 2, p = lane & 3;
    int mgrp = warp & 3, h = warp >> 2;
    int m0 = mgrp * 16;

    float acc[7][4];
#pragma unroll
    for (int i = 0; i < 7; i++)
#pragma unroll
        for (int j = 0; j < 4; j++) acc[i][j] = 0.f;

    const float* web = g_wep + (h * 7) * 15 * 128 + lane * 4;
#pragma unroll
    for (int ks = 0; ks < 15; ks++) {          // 15 x k16 over K=240
        float4 a0 = *(const float4*)(fs + (m0 + q) * ESA + ks * 16 + 4 * p);
        float4 a1 = *(const float4*)(fs + (m0 + q + 8) * ESA + ks * 16 + 4 * p);
#pragma unroll
        for (int nt = 0; nt < 7; nt++) {
            float4 bv = *(const float4*)(web + (nt * 15 + ks) * 128);
            MMA_TF32(acc[nt],
                     __float_as_uint(a0.x), __float_as_uint(a1.x),
                     __float_as_uint(a0.y), __float_as_uint(a1.y),
                     __float_as_uint(bv.x), __float_as_uint(bv.y));
            MMA_TF32(acc[nt],
                     __float_as_uint(a0.z), __float_as_uint(a1.z),
                     __float_as_uint(a0.w), __float_as_uint(a1.w),
                     __float_as_uint(bv.z), __float_as_uint(bv.w));
        }
    }

    int e1 = e0 + m0 + q, e2 = e1 + 8;
    int pos1 = nid[e1] * KSLOT + idxp[e1];
    int pos2 = nid[e2] * KSLOT + idxp[e2];
#pragma unroll
    for (int nt = 0; nt < 7; nt++) {
        int col = (h * 7 + nt) * 8 + 2 * p;
        if (col < HID) {
            float b0 = __ldg(lb + col), b1 = __ldg(lb + col + 1);
            *(float2*)(g_split + (size_t)pos1 * HID + col) =
                make_float2(acc[nt][0] + b0, acc[nt][1] + b1);
            *(float2*)(g_split + (size_t)pos2 * HID + col) =
                make_float2(acc[nt][2] + b0, acc[nt][3] + b1);
        }
    }
}

// ---------------------------------------------------------------- K2: column mixer v3 (8 nodes/block)
#define CMX_SMEM ((8 * 2080 + 512) * 4)

__global__ __launch_bounds__(256) void k_colmix(
    const float* __restrict__ cg, const float* __restrict__ cb,
    const float* __restrict__ cw1, const float* __restrict__ cb1,
    const float* __restrict__ cw2, const float* __restrict__ cb2)
{
    extern __shared__ float sm2[];
    float* t   = sm2;                  // 8 nodes x [20][104]
    float* w1s = sm2 + 8 * 2080;       // [200]
    float* w2s = w1s + 200;            // [200]
    float* gs  = w2s + 200;            // [20]
    float* bs  = gs + 20;              // [20]
    float* b1s = bs + 20;              // [10]
    float* b2s = b1s + 10;             // [20]
    int tid = threadIdx.x;
    float* base = g_split + (size_t)blockIdx.x * 8 * KSLOT * HID;

    for (int o = tid; o < 200; o += 256) { w1s[o] = cw1[o]; w2s[o] = cw2[o]; }
    if (tid < 20) { gs[tid] = cg[tid]; bs[tid] = cb[tid]; b2s[tid] = cb2[tid]; }
    if (tid >= 32 && tid < 42) b1s[tid - 32] = cb1[tid - 32];

    for (int o = tid; o < 4000; o += 256) {
        int node = o / 500, r = o % 500;
        int k = r / 25, c4 = r - k * 25;
        *(float4*)(t + node * 2080 + k * 104 + c4 * 4) =
            *(const float4*)(base + (node * KSLOT + k) * HID + c4 * 4);
    }
    __syncthreads();

    int node = tid >> 5, lane = tid & 31;
    float* tb = t + node * 2080;
#pragma unroll
    for (int i = 0; i < 4; i++) {
        int c = lane + 32 * i;
        if (c < HID) {
            float v[KSLOT]; float s = 0.f;
#pragma unroll
            for (int k = 0; k < KSLOT; k++) { v[k] = tb[k * 104 + c]; s += v[k]; }
            float mu = s * (1.0f / KSLOT);
            float s2 = 0.f;
#pragma unroll
            for (int k = 0; k < KSLOT; k++) { float d = v[k] - mu; s2 += d * d; }
            float rs = rsqrtf(s2 * (1.0f / KSLOT) + LN_EPS);

            float vn[KSLOT];
#pragma unroll
            for (int k = 0; k < KSLOT; k++) vn[k] = (v[k] - mu) * rs * gs[k] + bs[k];

            float h1[10];
#pragma unroll
            for (int m = 0; m < 10; m++) {
                float a = b1s[m];
#pragma unroll
                for (int k = 0; k < KSLOT; k++) a += w1s[m * KSLOT + k] * vn[k];
                h1[m] = gelu_fast(a);
            }
#pragma unroll
            for (int k = 0; k < KSLOT; k++) {
                float d = b2s[k];
#pragma unroll
                for (int m = 0; m < 10; m++) d += w2s[k * 10 + m] * h1[m];
                tb[k * 104 + c] = v[k] + d;
            }
        }
    }
    __syncthreads();

    for (int o = tid; o < 4000; o += 256) {
        int node = o / 500, r = o % 500;
        int k = r / 25, c4 = r - k * 25;
        *(float4*)(base + (node * KSLOT + k) * HID + c4 * 4) =
            *(const float4*)(t + node * 2080 + k * 104 + c4 * 4);
    }
}

// ---------------------------------------------------------------- K3: fused row mixer (tf32 mma, warp-pair cooperative)
// 64 rows/block, 128 threads = 2 pairs; pair owns 32 rows, warps split n-dim.
// Weights: fragment-linear LDG (one 512B contiguous block per warp request).
#define SA 112    // Yn stride (112 mod 32 = 16 -> LDS.128 conflict-free)
#define SH 80     // Hs stride (64 + 16)
#define NCHUNK 7  // 448 = 7*64
#define MIX_SMEM ((64*SA + 64*SH) * 4)   // 49152 B -> 4 blocks/SM

__global__ __launch_bounds__(128, 4) void k_mixer(
    const float* __restrict__ lng, const float* __restrict__ lnb,
    const float* __restrict__ b1, const float* __restrict__ b2)
{
    extern __shared__ float smx[];
    float* Yn = smx;                  // [64][SA]  (per-pair 32-row regions)
    float* Hs = smx + 64 * SA;        // [64][SH]

    int tid  = threadIdx.x;
    int warp = tid >> 5, lane = tid & 31;
    int q = lane >> 2, p = lane & 3;
    int pair = warp >> 1;             // 0,1
    int h    = warp & 1;              // n-half within pair
    int m0   = pair * 32;
    int barid = pair + 1;
    size_t rowBase = (size_t)blockIdx.x * 64;

    // ---- rowLN -> Yn: each warp does 16 rows (warp*16 covers pair's 32 rows) ----
    for (int rr = 0; rr < 16; rr++) {
        int row = warp * 16 + rr;
        const float* x = g_split + (rowBase + row) * HID;
        float v[4]; float s = 0.f, s2 = 0.f;
#pragma unroll
        for (int i = 0; i < 4; i++) {
            int c = lane + 32 * i;
            v[i] = (c < HID) ? x[c] : 0.f;
            s += v[i]; s2 += v[i] * v[i];
        }
#pragma unroll
        for (int off = 16; off; off >>= 1) {
            s  += __shfl_xor_sync(0xffffffffu, s,  off);
            s2 += __shfl_xor_sync(0xffffffffu, s2, off);
        }
        float mu = s * 0.01f;
        float rs = rsqrtf(s2 * 0.01f - mu * mu + LN_EPS);
#pragma unroll
        for (int i = 0; i < 4; i++) {
            int c = lane + 32 * i;
            if (c < HID)
                Yn[row * SA + kperm16(c)] =
                    f2tf_f((v[i] - mu) * rs * __ldg(lng + c) + __ldg(lnb + c));
        }
        if (lane < SA - HID) Yn[row * SA + kperm16(HID + lane)] = 0.f;
    }
    barpair(barid);   // pair's Yn complete

    float acc2[2][7][4];
#pragma unroll
    for (int mt = 0; mt < 2; mt++)
#pragma unroll
        for (int i = 0; i < 7; i++)
#pragma unroll
            for (int j = 0; j < 4; j++) acc2[mt][i][j] = 0.f;

    const float* ya0 = Yn + (m0 + q) * SA + 4 * p;       // mt0 rows
    const float* ya1 = Yn + (m0 + 16 + q) * SA + 4 * p;  // mt1 rows
    const float* ha0 = Hs + (m0 + q) * SH + 4 * p;
    const float* ha1 = Hs + (m0 + 16 + q) * SH + 4 * p;

#pragma unroll 1
    for (int ch = 0; ch < NCHUNK; ch++) {
        // ---- GEMM1: this warp's 32-col half, all 32 rows ----
        float acc1[2][4][4];
#pragma unroll
        for (int mt = 0; mt < 2; mt++)
#pragma unroll
            for (int nt = 0; nt < 4; nt++)
#pragma unroll
                for (int j = 0; j < 4; j++) acc1[mt][nt][j] = 0.f;

        const float* w1c = g_w1p + (ch * 2 + h) * 28 * 128 + lane * 4;
#pragma unroll
        for (int ks = 0; ks < 7; ks++) {
            float4 a00 = *(const float4*)(ya0 + ks * 16);
            float4 a01 = *(const float4*)(ya0 + 8 * SA + ks * 16);
            float4 a10 = *(const float4*)(ya1 + ks * 16);
            float4 a11 = *(const float4*)(ya1 + 8 * SA + ks * 16);
#pragma unroll
            for (int nt = 0; nt < 4; nt++) {
                float4 bv = *(const float4*)(w1c + (nt * 7 + ks) * 128);
                MMA_TF32(acc1[0][nt],
                         __float_as_uint(a00.x), __float_as_uint(a01.x),
                         __float_as_uint(a00.y), __float_as_uint(a01.y),
                         __float_as_uint(bv.x), __float_as_uint(bv.y));
                MMA_TF32(acc1[0][nt],
                         __float_as_uint(a00.z), __float_as_uint(a01.z),
                         __float_as_uint(a00.w), __float_as_uint(a01.w),
                         __float_as_uint(bv.z), __float_as_uint(bv.w));
                MMA_TF32(acc1[1][nt],
                         __float_as_uint(a10.x), __float_as_uint(a11.x),
                         __float_as_uint(a10.y), __float_as_uint(a11.y),
                         __float_as_uint(bv.x), __float_as_uint(bv.y));
                MMA_TF32(acc1[1][nt],
                         __float_as_uint(a10.z), __float_as_uint(a11.z),
                         __float_as_uint(a10.w), __float_as_uint(a11.w),
                         __float_as_uint(bv.z), __float_as_uint(bv.w));
            }
        }

        barpair(barid);   // partner's GEMM2 reads of prev Hs complete

        // ---- bias + gelu -> Hs (this warp's cols, both m-tiles) ----
#pragma unroll
        for (int nt = 0; nt < 4; nt++) {
            int cl0 = h * 32 + nt * 8 + 2 * p;
            int cg0 = ch * 64 + cl0;
            float bb0 = (cg0     < RH) ? __ldg(b1 + cg0)     : 0.f;
            float bb1 = (cg0 + 1 < RH) ? __ldg(b1 + cg0 + 1) : 0.f;
            int ps0 = kperm16(cl0), ps1 = kperm16(cl0 + 1);
#pragma unroll
            for (int mt = 0; mt < 2; mt++) {
                float* h0 = Hs + (m0 + mt * 16 + q) * SH;
                float* h1 = Hs + (m0 + mt * 16 + q + 8) * SH;
                h0[ps0] = f2tf_f(gelu_fast(acc1[mt][nt][0] + bb0));
                h0[ps1] = f2tf_f(gelu_fast(acc1[mt][nt][1] + bb1));
                h1[ps0] = f2tf_f(gelu_fast(acc1[mt][nt][2] + bb0));
                h1[ps1] = f2tf_f(gelu_fast(acc1[mt][nt][3] + bb1));
            }
        }

        barpair(barid);   // pair's H complete

        // ---- GEMM2: this warp's output tiles (h=0: 0..6, h=1: 7..12), 32 rows ----
        const float* w2c = g_w2p + (ch * 2 + h) * 28 * 128 + lane * 4;
#pragma unroll
        for (int ks = 0; ks < 4; ks++) {
            float4 a00 = *(const float4*)(ha0 + ks * 16);
            float4 a01 = *(const float4*)(ha0 + 8 * SH + ks * 16);
            float4 a10 = *(const float4*)(ha1 + ks * 16);
            float4 a11 = *(const float4*)(ha1 + 8 * SH + ks * 16);
#pragma unroll
            for (int nt = 0; nt < 7; nt++) {
                if (nt < 7 - h) {
                    float4 bv = *(const float4*)(w2c + (nt * 4 + ks) * 128);
                    MMA_TF32(acc2[0][nt],
                             __float_as_uint(a00.x), __float_as_uint(a01.x),
                             __float_as_uint(a00.y), __float_as_uint(a01.y),
                             __float_as_uint(bv.x), __float_as_uint(bv.y));
                    MMA_TF32(acc2[0][nt],
                             __float_as_uint(a00.z), __float_as_uint(a01.z),
                             __float_as_uint(a00.w), __float_as_uint(a01.w),
                             __float_as_uint(bv.z), __float_as_uint(bv.w));
                    MMA_TF32(acc2[1][nt],
                             __float_as_uint(a10.x), __float_as_uint(a11.x),
                             __float_as_uint(a10.y), __float_as_uint(a11.y),
                             __float_as_uint(bv.x), __float_as_uint(bv.y));
                    MMA_TF32(acc2[1][nt],
                             __float_as_uint(a10.z), __float_as_uint(a11.z),
                             __float_as_uint(a10.w), __float_as_uint(a11.w),
                             __float_as_uint(bv.z), __float_as_uint(bv.w));
                }
            }
        }
    }

    // ---- epilogue: + b2 + residual -> g_y (fp32), 32 rows, this warp's cols ----
#pragma unroll
    for (int nt = 0; nt < 7; nt++) {
        if (nt < 7 - h) {
            int col = (h * 7 + nt) * 8 + 2 * p;
            if (col < HID) {
                float bb0 = __ldg(b2 + col), bb1 = __ldg(b2 + col + 1);
#pragma unroll
                for (int mt = 0; mt < 2; mt++) {
                    size_t r0 = rowBase + m0 + mt * 16 + q, r1 = r0 + 8;
                    float2 x0 = *(const float2*)(g_split + r0 * HID + col);
                    float2 x1 = *(const float2*)(g_split + r1 * HID + col);
                    *(float2*)(g_y + r0 * HID + col) =
                        make_float2(acc2[mt][nt][0] + bb0 + x0.x, acc2[mt][nt][1] + bb1 + x0.y);
                    *(float2*)(g_y + r1 * HID + col) =
                        make_float2(acc2[mt][nt][2] + bb0 + x1.x, acc2[mt][nt][3] + bb1 + x1.y);
                }
            }
        }
    }
}

// ---------------------------------------------------------------- K4: final LN + mean over K + out proj
__global__ __launch_bounds__(128) void k_final(
    const float* __restrict__ ng, const float* __restrict__ nb,
    const float* __restrict__ ow, const float* __restrict__ ob,
    float* __restrict__ out)
{
    __shared__ float Mp[4][HID];
    __shared__ float Ms[HID];
    int n = blockIdx.x;
    int tid = threadIdx.x, warp = tid >> 5, lane = tid & 31;

    float psum[4] = {0.f, 0.f, 0.f, 0.f};
    for (int rr = 0; rr < 5; rr++) {
        int k = warp * 5 + rr;
        const float* x = g_y + (size_t)(n * KSLOT + k) * HID;
        float v[4]; float s = 0.f, s2 = 0.f;
#pragma unroll
        for (int i = 0; i < 4; i++) {
            int c = lane + 32 * i;
            v[i] = (c < HID) ? x[c] : 0.f;
            s += v[i]; s2 += v[i] * v[i];
        }
#pragma unroll
        for (int off = 16; off; off >>= 1) {
            s  += __shfl_xor_sync(0xffffffffu, s,  off);
            s2 += __shfl_xor_sync(0xffffffffu, s2, off);
        }
        float mu = s * 0.01f;
        float rs = rsqrtf(s2 * 0.01f - mu * mu + LN_EPS);
#pragma unroll
        for (int i = 0; i < 4; i++) {
            int c = lane + 32 * i;
            if (c < HID) psum[i] += (v[i] - mu) * rs * ng[c] + nb[c];
        }
    }
#pragma unroll
    for (int i = 0; i < 4; i++) {
        int c = lane + 32 * i;
        if (c < HID) Mp[warp][c] = psum[i];
    }
    __syncthreads();
    if (tid < HID) Ms[tid] = (Mp[0][tid] + Mp[1][tid] + Mp[2][tid] + Mp[3][tid]) * (1.0f / KSLOT);
    __syncthreads();

    for (int o = warp; o < HID; o += 4) {
        float a = 0.f;
#pragma unroll
        for (int i = 0; i < 4; i++) {
            int c = lane + 32 * i;
            if (c < HID) a += Ms[c] * ow[o * HID + c];
        }
#pragma unroll
        for (int off = 16; off; off >>= 1) a += __shfl_xor_sync(0xffffffffu, a, off);
        if (lane == 0) out[(size_t)n * HID + o] = a + ob[o];
    }
}

// ---------------------------------------------------------------- launch
extern "C" void kernel_launch(void* const* d_in, const int* in_sizes, int n_in,
                              void* d_out, int out_size)
{
    const float* ef       = (const float*)d_in[0];
    const float* et       = (const float*)d_in[1];
    const int*   nid      = (const int*)  d_in[2];
    const int*   idx      = (const int*)  d_in[3];
    const float* lin_w    = (const float*)d_in[4];
    const float* lin_b    = (const float*)d_in[5];
    const float* col_ln_g = (const float*)d_in[6];
    const float* col_ln_b = (const float*)d_in[7];
    const float* col_w1   = (const float*)d_in[8];
    const float* col_b1   = (const float*)d_in[9];
    const float* col_w2   = (const float*)d_in[10];
    const float* col_b2   = (const float*)d_in[11];
    const float* row_ln_g = (const float*)d_in[12];
    const float* row_ln_b = (const float*)d_in[13];
    const float* row_w1   = (const float*)d_in[14];
    const float* row_b1   = (const float*)d_in[15];
    const float* row_w2   = (const float*)d_in[16];
    const float* row_b2   = (const float*)d_in[17];
    const float* norm_g   = (const float*)d_in[18];
    const float* norm_b   = (const float*)d_in[19];
    const float* out_w    = (const float*)d_in[20];
    const float* out_b    = (const float*)d_in[21];
    float* out = (float*)d_out;

    cudaFuncSetAttribute((const void*)k_edge,   cudaFuncAttributeMaxDynamicSharedMemorySize, EDGE_SMEM);
    cudaFuncSetAttribute((const void*)k_colmix, cudaFuncAttributeMaxDynamicSharedMemorySize, CMX_SMEM);
    cudaFuncSetAttribute((const void*)k_mixer,  cudaFuncAttributeMaxDynamicSharedMemorySize, MIX_SMEM);

    k_init<<<(MROWS * HID / 4 + 255) / 256, 256>>>(row_w1, row_w2, lin_w);
    k_edge<<<E_EDGES / 64, 256, EDGE_SMEM>>>(ef, et, nid, idx, lin_b);
    k_colmix<<<N_N / 8, 256, CMX_SMEM>>>(col_ln_g, col_ln_b, col_w1, col_b1, col_w2, col_b2);
    k_mixer<<<MROWS / 64, 128, MIX_SMEM>>>(row_ln_g, row_ln_b, row_b1, row_b2);
    k_final<<<N_N, 128>>>(norm_g, norm_b, out_w, out_b, out);
}

// round 16
// speedup vs baseline: 1.1282x; 1.0278x over previous
#include <cuda_runtime.h>
#include <cuda_bf16.h>
#include <math.h>

#define E_EDGES 200000
#define N_N     20000
#define KSLOT   20
#define HID     100
#define TDIM    100
#define EFD     128
#define FIN     228          // EFD + TDIM
#define RH      400
#define MROWS   (N_N*KSLOT)  // 400000
#define LN_EPS  1e-5f

// scratch (device globals; no allocation allowed)
__device__ float g_split[(size_t)MROWS * HID];  // x: scatter target, colmix in-place, residual
__device__ float g_y[(size_t)MROWS * HID];      // mixer output X2
// fragment-linear weights: [(ch,h)][nt][ks][lane][4] -> warp B-request = 512B contiguous
__device__ float g_w1p[7 * 2 * 4 * 7 * 128];    // 50176
__device__ float g_w2p[7 * 2 * 7 * 4 * 128];    // 50176
__device__ float g_wep[2 * 7 * 15 * 128];       // 26880
__device__ float g_tw[128];                     // time-encode freqs (padded)

// fast gelu: tanh-form with HW tanh.approx (sm_75+), ~6 instr vs ~20 for erff
__device__ __forceinline__ float gelu_fast(float x) {
    float u = x * (0.7978845608028654f + 0.035677408136300125f * x * x);
    float t;
    asm("tanh.approx.f32 %0, %1;" : "=f"(t) : "f"(u));
    return 0.5f * x * (1.0f + t);
}

__device__ __forceinline__ unsigned f2tf(float v) {
    unsigned r;
    asm("cvt.rna.tf32.f32 %0, %1;" : "=r"(r) : "f"(v));
    return r;
}
__device__ __forceinline__ float f2tf_f(float v) { return __uint_as_float(f2tf(v)); }

// permute k within each 16-block: thread p's 4 frag elems (k = p, p+4, p+8, p+12) contiguous
__device__ __forceinline__ int kperm16(int k) {
    return (k & ~15) | (((k & 3) << 2) | ((k >> 2) & 3));
}

__device__ __forceinline__ void barpair(int id) {
    asm volatile("bar.sync %0, 64;" :: "r"(id) : "memory");
}

#define MMA_TF32(c,a0,a1,a2,a3,b0,b1) \
    asm volatile("mma.sync.aligned.m16n8k8.row.col.f32.tf32.tf32.f32 " \
        "{%0,%1,%2,%3}, {%4,%5,%6,%7}, {%8,%9}, {%0,%1,%2,%3};" \
        : "+f"(c[0]),"+f"(c[1]),"+f"(c[2]),"+f"(c[3]) \
        : "r"(a0),"r"(a1),"r"(a2),"r"(a3),"r"(b0),"r"(b1))

// ---------------------------------------------------------------- K0: init (zero split + fragment-linear weight prep)
__global__ void k_init(const float* __restrict__ w1, const float* __restrict__ w2,
                       const float* __restrict__ lw) {
    int i = blockIdx.x * 256 + threadIdx.x;
    const int n4 = MROWS * HID / 4;            // 10,000,000
    if (i < n4) ((float4*)g_split)[i] = make_float4(0.f, 0.f, 0.f, 0.f);

    // W1: [(ch,h)][nt(4)][ks(7)][lane][e]; value W1[n][k], n=ch*64+h*32+nt*8+q, k=ks*16+p+4e
    // (matches perm16 Yn A-fragments)
    if (i < 7 * 2 * 4 * 7 * 128) {
        int e = i & 3, lane = (i >> 2) & 31;
        int t = i >> 7;
        int ks = t % 7; t /= 7;
        int nt = t & 3; t >>= 2;
        int h = t & 1, ch = t >> 1;
        int q = lane >> 2, p = lane & 3;
        int n = ch * 64 + h * 32 + nt * 8 + q;
        int k = ks * 16 + p + 4 * e;
        g_w1p[i] = f2tf_f((n < RH && k < HID) ? w1[n * HID + k] : 0.f);
    }
    // W2: [(ch,h)][nt(7)][ks(4)][lane][e]; value W2[n][k], n=(h*7+nt)*8+q, k=ch*64+ks*16+4p+e
    // (matches IDENTITY-layout H A-fragments: slot (p,e) <-> logical col 4p+e)
    if (i < 7 * 2 * 7 * 4 * 128) {
        int e = i & 3, lane = (i >> 2) & 31;
        int t = i >> 7;
        int ks = t & 3; t >>= 2;
        int nt = t % 7; t /= 7;
        int h = t & 1, ch = t >> 1;
        int q = lane >> 2, p = lane & 3;
        int n = (h * 7 + nt) * 8 + q;
        int k = ch * 64 + ks * 16 + 4 * p + e;
        g_w2p[i] = f2tf_f((n < HID && k < RH) ? w2[n * RH + k] : 0.f);
    }
    // edge W: [h(2)][nt(7)][ks(15)][lane][e]; value lw[n][k], n=(h*7+nt)*8+q, k=ks*16+p+4e
    if (i < 2 * 7 * 15 * 128) {
        int e = i & 3, lane = (i >> 2) & 31;
        int t = i >> 7;
        int ks = t % 15; t /= 15;
        int nt = t % 7;
        int h = t / 7;
        int q = lane >> 2, p = lane & 3;
        int n = (h * 7 + nt) * 8 + q;
        int k = ks * 16 + p + 4 * e;
        g_wep[i] = f2tf_f((n < HID && k < FIN) ? lw[n * FIN + k] : 0.f);
    }
    if (i < 128) g_tw[i] = (i < TDIM) ? exp10f(-(9.0f / 99.0f) * (float)i) : 0.f;
}

// ---------------------------------------------------------------- K1: edge MLP (tf32 mma) + scatter
// 64 edges/block, 256 threads = 8 warps = 4 m-groups (16 edges) x 2 n-halves.
#define ESA 240          // fs stride (240 mod 32 = 16 -> LDS.128 conflict-free)
#define EDGE_SMEM (64 * ESA * 4)   // 61440 B -> 2 blocks/SM

__global__ __launch_bounds__(256, 2) void k_edge(
    const float* __restrict__ ef, const float* __restrict__ et,
    const int* __restrict__ nid, const int* __restrict__ idxp,
    const float* __restrict__ lb)
{
    extern __shared__ float fs[];    // [64][240] tf32, perm16
    int tid = threadIdx.x;
    int e0 = blockIdx.x * 64;

    for (int o = tid; o < 64 * 32; o += 256) {
        int e = o >> 5, j4 = o & 31;
        float4 v = ((const float4*)ef)[(size_t)(e0 + e) * 32 + j4];
        float* dst = fs + e * ESA;
        int k0 = j4 * 4;
        dst[kperm16(k0)]     = f2tf_f(v.x);
        dst[kperm16(k0 + 1)] = f2tf_f(v.y);
        dst[kperm16(k0 + 2)] = f2tf_f(v.z);
        dst[kperm16(k0 + 3)] = f2tf_f(v.w);
    }
    for (int o = tid; o < 64 * 112; o += 256) {
        int e = o / 112, tt = o - e * 112;
        float val = 0.f;
        if (tt < TDIM) val = __cosf(et[e0 + e] * __ldg(g_tw + tt));
        fs[e * ESA + kperm16(128 + tt)] = f2tf_f(val);
    }
    __syncthreads();

    int warp = tid >> 5, lane = tid & 31;
    int q = lane >> 2, p = lane & 3;
    int mgrp = warp & 3, h = warp >> 2;
    int m0 = mgrp * 16;

    float acc[7][4];
#pragma unroll
    for (int i = 0; i < 7; i++)
#pragma unroll
        for (int j = 0; j < 4; j++) acc[i][j] = 0.f;

    const float* web = g_wep + (h * 7) * 15 * 128 + lane * 4;
#pragma unroll
    for (int ks = 0; ks < 15; ks++) {          // 15 x k16 over K=240
        float4 a0 = *(const float4*)(fs + (m0 + q) * ESA + ks * 16 + 4 * p);
        float4 a1 = *(const float4*)(fs + (m0 + q + 8) * ESA + ks * 16 + 4 * p);
#pragma unroll
        for (int nt = 0; nt < 7; nt++) {
            float4 bv = *(const float4*)(web + (nt * 15 + ks) * 128);
            MMA_TF32(acc[nt],
                     __float_as_uint(a0.x), __float_as_uint(a1.x),
                     __float_as_uint(a0.y), __float_as_uint(a1.y),
                     __float_as_uint(bv.x), __float_as_uint(bv.y));
            MMA_TF32(acc[nt],
                     __float_as_uint(a0.z), __float_as_uint(a1.z),
                     __float_as_uint(a0.w), __float_as_uint(a1.w),
                     __float_as_uint(bv.z), __float_as_uint(bv.w));
        }
    }

    int e1 = e0 + m0 + q, e2 = e1 + 8;
    int pos1 = nid[e1] * KSLOT + idxp[e1];
    int pos2 = nid[e2] * KSLOT + idxp[e2];
#pragma unroll
    for (int nt = 0; nt < 7; nt++) {
        int col = (h * 7 + nt) * 8 + 2 * p;
        if (col < HID) {
            float b0 = __ldg(lb + col), b1 = __ldg(lb + col + 1);
            *(float2*)(g_split + (size_t)pos1 * HID + col) =
                make_float2(acc[nt][0] + b0, acc[nt][1] + b1);
            *(float2*)(g_split + (size_t)pos2 * HID + col) =
                make_float2(acc[nt][2] + b0, acc[nt][3] + b1);
        }
    }
}

// ---------------------------------------------------------------- K2: column mixer v3 (8 nodes/block)
#define CMX_SMEM ((8 * 2080 + 512) * 4)

__global__ __launch_bounds__(256) void k_colmix(
    const float* __restrict__ cg, const float* __restrict__ cb,
    const float* __restrict__ cw1, const float* __restrict__ cb1,
    const float* __restrict__ cw2, const float* __restrict__ cb2)
{
    extern __shared__ float sm2[];
    float* t   = sm2;                  // 8 nodes x [20][104]
    float* w1s = sm2 + 8 * 2080;       // [200]
    float* w2s = w1s + 200;            // [200]
    float* gs  = w2s + 200;            // [20]
    float* bs  = gs + 20;              // [20]
    float* b1s = bs + 20;              // [10]
    float* b2s = b1s + 10;             // [20]
    int tid = threadIdx.x;
    float* base = g_split + (size_t)blockIdx.x * 8 * KSLOT * HID;

    for (int o = tid; o < 200; o += 256) { w1s[o] = cw1[o]; w2s[o] = cw2[o]; }
    if (tid < 20) { gs[tid] = cg[tid]; bs[tid] = cb[tid]; b2s[tid] = cb2[tid]; }
    if (tid >= 32 && tid < 42) b1s[tid - 32] = cb1[tid - 32];

    for (int o = tid; o < 4000; o += 256) {
        int node = o / 500, r = o % 500;
        int k = r / 25, c4 = r - k * 25;
        *(float4*)(t + node * 2080 + k * 104 + c4 * 4) =
            *(const float4*)(base + (node * KSLOT + k) * HID + c4 * 4);
    }
    __syncthreads();

    int node = tid >> 5, lane = tid & 31;
    float* tb = t + node * 2080;
#pragma unroll
    for (int i = 0; i < 4; i++) {
        int c = lane + 32 * i;
        if (c < HID) {
            float v[KSLOT]; float s = 0.f;
#pragma unroll
            for (int k = 0; k < KSLOT; k++) { v[k] = tb[k * 104 + c]; s += v[k]; }
            float mu = s * (1.0f / KSLOT);
            float s2 = 0.f;
#pragma unroll
            for (int k = 0; k < KSLOT; k++) { float d = v[k] - mu; s2 += d * d; }
            float rs = rsqrtf(s2 * (1.0f / KSLOT) + LN_EPS);

            float vn[KSLOT];
#pragma unroll
            for (int k = 0; k < KSLOT; k++) vn[k] = (v[k] - mu) * rs * gs[k] + bs[k];

            float h1[10];
#pragma unroll
            for (int m = 0; m < 10; m++) {
                float a = b1s[m];
#pragma unroll
                for (int k = 0; k < KSLOT; k++) a += w1s[m * KSLOT + k] * vn[k];
                h1[m] = gelu_fast(a);
            }
#pragma unroll
            for (int k = 0; k < KSLOT; k++) {
                float d = b2s[k];
#pragma unroll
                for (int m = 0; m < 10; m++) d += w2s[k * 10 + m] * h1[m];
                tb[k * 104 + c] = v[k] + d;
            }
        }
    }
    __syncthreads();

    for (int o = tid; o < 4000; o += 256) {
        int node = o / 500, r = o % 500;
        int k = r / 25, c4 = r - k * 25;
        *(float4*)(base + (node * KSLOT + k) * HID + c4 * 4) =
            *(const float4*)(t + node * 2080 + k * 104 + c4 * 4);
    }
}

// ---------------------------------------------------------------- K3: fused row mixer (tf32 mma, warp-pair cooperative)
// 64 rows/block, 128 threads = 2 pairs; pair owns 32 rows, warps split n-dim.
// Weights: fragment-linear LDG. H stored in IDENTITY layout (STS.64 writes);
// W2 fragments pre-permuted to match (slot (p,e) <-> logical col 4p+e).
#define SA 112    // Yn stride (112 mod 32 = 16 -> LDS.128 conflict-free)
#define SH 80     // Hs stride (64 + 16)
#define NCHUNK 7  // 448 = 7*64
#define MIX_SMEM ((64*SA + 64*SH) * 4)   // 49152 B -> 4 blocks/SM

__global__ __launch_bounds__(128, 4) void k_mixer(
    const float* __restrict__ lng, const float* __restrict__ lnb,
    const float* __restrict__ b1, const float* __restrict__ b2)
{
    extern __shared__ float smx[];
    float* Yn = smx;                  // [64][SA]  (per-pair 32-row regions)
    float* Hs = smx + 64 * SA;        // [64][SH]  identity col layout

    int tid  = threadIdx.x;
    int warp = tid >> 5, lane = tid & 31;
    int q = lane >> 2, p = lane & 3;
    int pair = warp >> 1;             // 0,1
    int h    = warp & 1;              // n-half within pair
    int m0   = pair * 32;
    int barid = pair + 1;
    size_t rowBase = (size_t)blockIdx.x * 64;

    // ---- rowLN -> Yn: each warp does 16 rows (warp*16 covers pair's 32 rows) ----
    for (int rr = 0; rr < 16; rr++) {
        int row = warp * 16 + rr;
        const float* x = g_split + (rowBase + row) * HID;
        float v[4]; float s = 0.f, s2 = 0.f;
#pragma unroll
        for (int i = 0; i < 4; i++) {
            int c = lane + 32 * i;
            v[i] = (c < HID) ? x[c] : 0.f;
            s += v[i]; s2 += v[i] * v[i];
        }
#pragma unroll
        for (int off = 16; off; off >>= 1) {
            s  += __shfl_xor_sync(0xffffffffu, s,  off);
            s2 += __shfl_xor_sync(0xffffffffu, s2, off);
        }
        float mu = s * 0.01f;
        float rs = rsqrtf(s2 * 0.01f - mu * mu + LN_EPS);
#pragma unroll
        for (int i = 0; i < 4; i++) {
            int c = lane + 32 * i;
            if (c < HID)
                Yn[row * SA + kperm16(c)] =
                    f2tf_f((v[i] - mu) * rs * __ldg(lng + c) + __ldg(lnb + c));
        }
        if (lane < SA - HID) Yn[row * SA + kperm16(HID + lane)] = 0.f;
    }
    barpair(barid);   // pair's Yn complete

    float acc2[2][7][4];
#pragma unroll
    for (int mt = 0; mt < 2; mt++)
#pragma unroll
        for (int i = 0; i < 7; i++)
#pragma unroll
            for (int j = 0; j < 4; j++) acc2[mt][i][j] = 0.f;

    const float* ya0 = Yn + (m0 + q) * SA + 4 * p;       // mt0 rows
    const float* ya1 = Yn + (m0 + 16 + q) * SA + 4 * p;  // mt1 rows
    const float* ha0 = Hs + (m0 + q) * SH + 4 * p;
    const float* ha1 = Hs + (m0 + 16 + q) * SH + 4 * p;

#pragma unroll 1
    for (int ch = 0; ch < NCHUNK; ch++) {
        // ---- GEMM1: this warp's 32-col half, all 32 rows ----
        float acc1[2][4][4];
#pragma unroll
        for (int mt = 0; mt < 2; mt++)
#pragma unroll
            for (int nt = 0; nt < 4; nt++)
#pragma unroll
                for (int j = 0; j < 4; j++) acc1[mt][nt][j] = 0.f;

        const float* w1c = g_w1p + (ch * 2 + h) * 28 * 128 + lane * 4;
#pragma unroll
        for (int ks = 0; ks < 7; ks++) {
            float4 a00 = *(const float4*)(ya0 + ks * 16);
            float4 a01 = *(const float4*)(ya0 + 8 * SA + ks * 16);
            float4 a10 = *(const float4*)(ya1 + ks * 16);
            float4 a11 = *(const float4*)(ya1 + 8 * SA + ks * 16);
#pragma unroll
            for (int nt = 0; nt < 4; nt++) {
                float4 bv = *(const float4*)(w1c + (nt * 7 + ks) * 128);
                MMA_TF32(acc1[0][nt],
                         __float_as_uint(a00.x), __float_as_uint(a01.x),
                         __float_as_uint(a00.y), __float_as_uint(a01.y),
                         __float_as_uint(bv.x), __float_as_uint(bv.y));
                MMA_TF32(acc1[0][nt],
                         __float_as_uint(a00.z), __float_as_uint(a01.z),
                         __float_as_uint(a00.w), __float_as_uint(a01.w),
                         __float_as_uint(bv.z), __float_as_uint(bv.w));
                MMA_TF32(acc1[1][nt],
                         __float_as_uint(a10.x), __float_as_uint(a11.x),
                         __float_as_uint(a10.y), __float_as_uint(a11.y),
                         __float_as_uint(bv.x), __float_as_uint(bv.y));
                MMA_TF32(acc1[1][nt],
                         __float_as_uint(a10.z), __float_as_uint(a11.z),
                         __float_as_uint(a10.w), __float_as_uint(a11.w),
                         __float_as_uint(bv.z), __float_as_uint(bv.w));
            }
        }

        barpair(barid);   // partner's GEMM2 reads of prev Hs complete

        // ---- bias + gelu -> Hs (identity layout, STS.64) ----
#pragma unroll
        for (int nt = 0; nt < 4; nt++) {
            int cl0 = h * 32 + nt * 8 + 2 * p;            // identity col position
            int cg0 = ch * 64 + cl0;
            float bb0 = (cg0     < RH) ? __ldg(b1 + cg0)     : 0.f;
            float bb1 = (cg0 + 1 < RH) ? __ldg(b1 + cg0 + 1) : 0.f;
#pragma unroll
            for (int mt = 0; mt < 2; mt++) {
                float* h0 = Hs + (m0 + mt * 16 + q) * SH + cl0;
                float* h1 = Hs + (m0 + mt * 16 + q + 8) * SH + cl0;
                *(float2*)h0 = make_float2(f2tf_f(gelu_fast(acc1[mt][nt][0] + bb0)),
                                           f2tf_f(gelu_fast(acc1[mt][nt][1] + bb1)));
                *(float2*)h1 = make_float2(f2tf_f(gelu_fast(acc1[mt][nt][2] + bb0)),
                                           f2tf_f(gelu_fast(acc1[mt][nt][3] + bb1)));
            }
        }

        barpair(barid);   // pair's H complete

        // ---- GEMM2: this warp's output tiles (h=0: 0..6, h=1: 7..12), 32 rows ----
        const float* w2c = g_w2p + (ch * 2 + h) * 28 * 128 + lane * 4;
#pragma unroll
        for (int ks = 0; ks < 4; ks++) {
            float4 a00 = *(const float4*)(ha0 + ks * 16);
            float4 a01 = *(const float4*)(ha0 + 8 * SH + ks * 16);
            float4 a10 = *(const float4*)(ha1 + ks * 16);
            float4 a11 = *(const float4*)(ha1 + 8 * SH + ks * 16);
#pragma unroll
            for (int nt = 0; nt < 7; nt++) {
                if (nt < 7 - h) {
                    float4 bv = *(const float4*)(w2c + (nt * 4 + ks) * 128);
                    MMA_TF32(acc2[0][nt],
                             __float_as_uint(a00.x), __float_as_uint(a01.x),
                             __float_as_uint(a00.y), __float_as_uint(a01.y),
                             __float_as_uint(bv.x), __float_as_uint(bv.y));
                    MMA_TF32(acc2[0][nt],
                             __float_as_uint(a00.z), __float_as_uint(a01.z),
                             __float_as_uint(a00.w), __float_as_uint(a01.w),
                             __float_as_uint(bv.z), __float_as_uint(bv.w));
                    MMA_TF32(acc2[1][nt],
                             __float_as_uint(a10.x), __float_as_uint(a11.x),
                             __float_as_uint(a10.y), __float_as_uint(a11.y),
                             __float_as_uint(bv.x), __float_as_uint(bv.y));
                    MMA_TF32(acc2[1][nt],
                             __float_as_uint(a10.z), __float_as_uint(a11.z),
                             __float_as_uint(a10.w), __float_as_uint(a11.w),
                             __float_as_uint(bv.z), __float_as_uint(bv.w));
                }
            }
        }
    }

    // ---- epilogue: + b2 + residual -> g_y (fp32), 32 rows, this warp's cols ----
#pragma unroll
    for (int nt = 0; nt < 7; nt++) {
        if (nt < 7 - h) {
            int col = (h * 7 + nt) * 8 + 2 * p;
            if (col < HID) {
                float bb0 = __ldg(b2 + col), bb1 = __ldg(b2 + col + 1);
#pragma unroll
                for (int mt = 0; mt < 2; mt++) {
                    size_t r0 = rowBase + m0 + mt * 16 + q, r1 = r0 + 8;
                    float2 x0 = *(const float2*)(g_split + r0 * HID + col);
                    float2 x1 = *(const float2*)(g_split + r1 * HID + col);
                    *(float2*)(g_y + r0 * HID + col) =
                        make_float2(acc2[mt][nt][0] + bb0 + x0.x, acc2[mt][nt][1] + bb1 + x0.y);
                    *(float2*)(g_y + r1 * HID + col) =
                        make_float2(acc2[mt][nt][2] + bb0 + x1.x, acc2[mt][nt][3] + bb1 + x1.y);
                }
            }
        }
    }
}

// ---------------------------------------------------------------- K4: final LN + mean over K + out proj
__global__ __launch_bounds__(128) void k_final(
    const float* __restrict__ ng, const float* __restrict__ nb,
    const float* __restrict__ ow, const float* __restrict__ ob,
    float* __restrict__ out)
{
    __shared__ float Mp[4][HID];
    __shared__ float Ms[HID];
    int n = blockIdx.x;
    int tid = threadIdx.x, warp = tid >> 5, lane = tid & 31;

    float psum[4] = {0.f, 0.f, 0.f, 0.f};
    for (int rr = 0; rr < 5; rr++) {
        int k = warp * 5 + rr;
        const float* x = g_y + (size_t)(n * KSLOT + k) * HID;
        float v[4]; float s = 0.f, s2 = 0.f;
#pragma unroll
        for (int i = 0; i < 4; i++) {
            int c = lane + 32 * i;
            v[i] = (c < HID) ? x[c] : 0.f;
            s += v[i]; s2 += v[i] * v[i];
        }
#pragma unroll
        for (int off = 16; off; off >>= 1) {
            s  += __shfl_xor_sync(0xffffffffu, s,  off);
            s2 += __shfl_xor_sync(0xffffffffu, s2, off);
        }
        float mu = s * 0.01f;
        float rs = rsqrtf(s2 * 0.01f - mu * mu + LN_EPS);
#pragma unroll
        for (int i = 0; i < 4; i++) {
            int c = lane + 32 * i;
            if (c < HID) psum[i] += (v[i] - mu) * rs * ng[c] + nb[c];
        }
    }
#pragma unroll
    for (int i = 0; i < 4; i++) {
        int c = lane + 32 * i;
        if (c < HID) Mp[warp][c] = psum[i];
    }
    __syncthreads();
    if (tid < HID) Ms[tid] = (Mp[0][tid] + Mp[1][tid] + Mp[2][tid] + Mp[3][tid]) * (1.0f / KSLOT);
    __syncthreads();

    for (int o = warp; o < HID; o += 4) {
        float a = 0.f;
#pragma unroll
        for (int i = 0; i < 4; i++) {
            int c = lane + 32 * i;
            if (c < HID) a += Ms[c] * ow[o * HID + c];
        }
#pragma unroll
        for (int off = 16; off; off >>= 1) a += __shfl_xor_sync(0xffffffffu, a, off);
        if (lane == 0) out[(size_t)n * HID + o] = a + ob[o];
    }
}

// ---------------------------------------------------------------- launch
extern "C" void kernel_launch(void* const* d_in, const int* in_sizes, int n_in,
                              void* d_out, int out_size)
{
    const float* ef       = (const float*)d_in[0];
    const float* et       = (const float*)d_in[1];
    const int*   nid      = (const int*)  d_in[2];
    const int*   idx      = (const int*)  d_in[3];
    const float* lin_w    = (const float*)d_in[4];
    const float* lin_b    = (const float*)d_in[5];
    const float* col_ln_g = (const float*)d_in[6];
    const float* col_ln_b = (const float*)d_in[7];
    const float* col_w1   = (const float*)d_in[8];
    const float* col_b1   = (const float*)d_in[9];
    const float* col_w2   = (const float*)d_in[10];
    const float* col_b2   = (const float*)d_in[11];
    const float* row_ln_g = (const float*)d_in[12];
    const float* row_ln_b = (const float*)d_in[13];
    const float* row_w1   = (const float*)d_in[14];
    const float* row_b1   = (const float*)d_in[15];
    const float* row_w2   = (const float*)d_in[16];
    const float* row_b2   = (const float*)d_in[17];
    const float* norm_g   = (const float*)d_in[18];
    const float* norm_b   = (const float*)d_in[19];
    const float* out_w    = (const float*)d_in[20];
    const float* out_b    = (const float*)d_in[21];
    float* out = (float*)d_out;

    cudaFuncSetAttribute((const void*)k_edge,   cudaFuncAttributeMaxDynamicSharedMemorySize, EDGE_SMEM);
    cudaFuncSetAttribute((const void*)k_colmix, cudaFuncAttributeMaxDynamicSharedMemorySize, CMX_SMEM);
    cudaFuncSetAttribute((const void*)k_mixer,  cudaFuncAttributeMaxDynamicSharedMemorySize, MIX_SMEM);

    k_init<<<(MROWS * HID / 4 + 255) / 256, 256>>>(row_w1, row_w2, lin_w);
    k_edge<<<E_EDGES / 64, 256, EDGE_SMEM>>>(ef, et, nid, idx, lin_b);
    k_colmix<<<N_N / 8, 256, CMX_SMEM>>>(col_ln_g, col_ln_b, col_w1, col_b1, col_w2, col_b2);
    k_mixer<<<MROWS / 64, 128, MIX_SMEM>>>(row_ln_g, row_ln_b, row_b1, row_b2);
    k_final<<<N_N, 128>>>(norm_g, norm_b, out_w, out_b, out);
}